// round 4
// baseline (speedup 1.0000x reference)
#include <cuda_runtime.h>
#include <math.h>
#include <stdint.h>

#define BB 2
#define SS 2048
#define DD 1024
#define HH 16
#define DHD 64
#define RR 256
#define NEXP 16
#define NKK 4096
#define TK 8

// ---------------- scratch (device globals; no allocation allowed) -------------
__device__ float g_nx [BB*SS*DD];
__device__ float g_nx2[BB*SS*DD];
__device__ float g_w  [4*BB*NEXP];
__device__ float g_wm [BB*NEXP];
__device__ float g_sc [BB*DD*RR];
__device__ float g_mc [BB*DD*RR];
__device__ float g_h  [BB*SS*RR];
__device__ float g_qm [BB*SS*RR];
__device__ float g_eq [BB*RR*DD];
__device__ float g_ek [BB*RR*DD];
__device__ float g_ev [BB*RR*DD];
__device__ float g_q  [BB*SS*DD];
__device__ float g_k  [BB*SS*DD];
__device__ float g_v  [BB*SS*DD];
__device__ float g_ao [BB*SS*DD];
__device__ float g_x1 [BB*SS*DD];
__device__ float g_ms [(size_t)BB*SS*NKK];

// ---------------- utility ------------------------------------------------------
__global__ void zero_kernel(float* p, int n) {
    int i = blockIdx.x * blockDim.x + threadIdx.x;
    if (i < n) p[i] = 0.f;
}

// ---------------- LayerNorm: one block per row, 256 threads --------------------
__global__ void __launch_bounds__(256) ln_kernel(const float* __restrict__ x,
                                                 const float* __restrict__ g,
                                                 const float* __restrict__ b,
                                                 float* __restrict__ out) {
    int row = blockIdx.x;
    const float4* xr = (const float4*)(x + (size_t)row * DD);
    float4 t = xr[threadIdx.x];
    float s  = t.x + t.y + t.z + t.w;
    float sq = t.x*t.x + t.y*t.y + t.z*t.z + t.w*t.w;
    __shared__ float rs[8], rq[8];
    for (int o = 16; o; o >>= 1) {
        s  += __shfl_down_sync(0xffffffffu, s,  o);
        sq += __shfl_down_sync(0xffffffffu, sq, o);
    }
    int wid = threadIdx.x >> 5, lane = threadIdx.x & 31;
    if (lane == 0) { rs[wid] = s; rq[wid] = sq; }
    __syncthreads();
    if (threadIdx.x == 0) {
        float a = 0.f, c = 0.f;
        for (int i = 0; i < 8; i++) { a += rs[i]; c += rq[i]; }
        rs[0] = a; rq[0] = c;
    }
    __syncthreads();
    float mean = rs[0] * (1.f / DD);
    float var  = rq[0] * (1.f / DD) - mean * mean;
    float rstd = rsqrtf(var + 1e-5f);
    float4 gg = ((const float4*)g)[threadIdx.x];
    float4 bb = ((const float4*)b)[threadIdx.x];
    float4 o4;
    o4.x = (t.x - mean) * rstd * gg.x + bb.x;
    o4.y = (t.y - mean) * rstd * gg.y + bb.y;
    o4.z = (t.z - mean) * rstd * gg.z + bb.z;
    o4.w = (t.w - mean) * rstd * gg.w + bb.w;
    ((float4*)(out + (size_t)row * DD))[threadIdx.x] = o4;
}

// ---------------- routing: per-token softmax over 16 experts, pooled -----------
__global__ void __launch_bounds__(128) route_kernel(
    const float* __restrict__ nx, const float* __restrict__ imp,
    const float* __restrict__ W0, const float* __restrict__ W1,
    const float* __restrict__ W2, const float* __restrict__ W3,
    int nW, float* __restrict__ wacc) {
    int token = blockIdx.x;
    int b = token / SS;
    __shared__ float xr[DD];
    __shared__ float lg[64];
    const float* row = nx + (size_t)token * DD;
    for (int i = threadIdx.x; i < DD; i += 128) xr[i] = row[i];
    __syncthreads();
    int wid = threadIdx.x >> 5, lane = threadIdx.x & 31;
    const float* Ws[4] = {W0, W1, W2, W3};
    for (int l = wid; l < nW * NEXP; l += 4) {
        const float* wr = Ws[l >> 4] + (size_t)(l & 15) * DD;
        float s = 0.f;
        for (int d = lane; d < DD; d += 32) s += xr[d] * wr[d];
        for (int o = 16; o; o >>= 1) s += __shfl_down_sync(0xffffffffu, s, o);
        if (lane == 0) lg[l] = s;
    }
    __syncthreads();
    if (threadIdx.x < nW) {
        int r = threadIdx.x;
        float mx = -1e30f;
        for (int n = 0; n < NEXP; n++) mx = fmaxf(mx, lg[r * NEXP + n]);
        float e[NEXP], sum = 0.f;
        for (int n = 0; n < NEXP; n++) { e[n] = expf(lg[r * NEXP + n] - mx); sum += e[n]; }
        float w = imp[token] / sum;
        for (int n = 0; n < NEXP; n++)
            atomicAdd(&wacc[(r * BB + b) * NEXP + n], e[n] * w);
    }
}

__global__ void norm_kernel(float* w, int cnt) {
    int i = threadIdx.x;
    if (i < cnt) {
        float* p = w + i * NEXP;
        float s = 0.f;
        for (int n = 0; n < NEXP; n++) s += p[n];
        float inv = 1.f / (s + 1e-8f);
        for (int n = 0; n < NEXP; n++) p[n] *= inv;
    }
}

// ---------------- pool mixes: out[b, r] = sum_n w[b,n] * P[n, r] ---------------
__global__ void __launch_bounds__(256) mix_kernel(const float* __restrict__ w,
                                                  const float* __restrict__ P,
                                                  float* __restrict__ out) {
    const size_t X = (size_t)DD * RR;
    size_t idx = (size_t)blockIdx.x * 256 + threadIdx.x;
    int b = (int)(idx / X);
    size_t r = idx % X;
    float acc = 0.f;
#pragma unroll
    for (int n = 0; n < NEXP; n++) acc += w[b * NEXP + n] * P[(size_t)n * X + r];
    out[idx] = acc;
}

__global__ void __launch_bounds__(256) mix3_kernel(
    const float* __restrict__ wq, const float* __restrict__ wk,
    const float* __restrict__ wv, const float* __restrict__ P,
    float* __restrict__ eq, float* __restrict__ ek, float* __restrict__ ev) {
    const size_t X = (size_t)RR * DD;
    size_t idx = (size_t)blockIdx.x * 256 + threadIdx.x;
    int b = (int)(idx / X);
    size_t r = idx % X;
    float aq = 0.f, ak = 0.f, av = 0.f;
#pragma unroll
    for (int n = 0; n < NEXP; n++) {
        float p = P[(size_t)n * X + r];
        aq += wq[b * NEXP + n] * p;
        ak += wk[b * NEXP + n] * p;
        av += wv[b * NEXP + n] * p;
    }
    eq[idx] = aq; ek[idx] = ak; ev[idx] = av;
}

// ---------------- SGEMM: 128x128x16 tile, 256 threads, 8x8 microtile -----------
// Register-prefetched pipeline: global loads of k-tile t+1 overlap compute of t.
// TRANSB=false: B is [K,N] row-major. TRANSB=true: B is [N,K] row-major.
// C = alpha * A*B (+ res). M,N multiple of 128; K multiple of 16.
template<bool TRANSB, bool RES>
__global__ void __launch_bounds__(256, 2) sgemm_kernel(
    const float* __restrict__ A, const float* __restrict__ B,
    const float* __restrict__ resp, float* __restrict__ C,
    int M, int N, int K, float alpha,
    long sA, long sB, long sC, long sR) {
    int bz = blockIdx.z;
    A += (size_t)bz * sA;
    B += (size_t)bz * sB;
    C += (size_t)bz * sC;
    if (RES) resp += (size_t)bz * sR;
    int n0 = blockIdx.x * 128, m0 = blockIdx.y * 128;
    __shared__ float As[16][128];
    __shared__ float Bs[16][128];
    int tid = threadIdx.x;
    int tx = tid & 15, ty = tid >> 4;
    // per-thread load coordinates (fixed across k-tiles)
    int rA0 = tid >> 2,          cA0 = tid & 3;          // A: f = tid
    int rA1 = (tid + 256) >> 2,  cA1 = (tid + 256) & 3;  //    f = tid+256
    int rBn0 = tid >> 5,         cBn0 = tid & 31;        // B NN
    int rBn1 = (tid + 256) >> 5, cBn1 = (tid + 256) & 31;
    int rBt0 = rA0, cBt0 = cA0;                          // B NT
    int rBt1 = rA1, cBt1 = cA1;

    float acc[8][8];
#pragma unroll
    for (int i = 0; i < 8; i++)
#pragma unroll
        for (int j = 0; j < 8; j++) acc[i][j] = 0.f;

    float4 pa[2], pb[2];
    // prefetch first tile
    pa[0] = *(const float4*)(A + (size_t)(m0 + rA0) * K + cA0 * 4);
    pa[1] = *(const float4*)(A + (size_t)(m0 + rA1) * K + cA1 * 4);
    if (!TRANSB) {
        pb[0] = *(const float4*)(B + (size_t)rBn0 * N + n0 + cBn0 * 4);
        pb[1] = *(const float4*)(B + (size_t)rBn1 * N + n0 + cBn1 * 4);
    } else {
        pb[0] = *(const float4*)(B + (size_t)(n0 + rBt0) * K + cBt0 * 4);
        pb[1] = *(const float4*)(B + (size_t)(n0 + rBt1) * K + cBt1 * 4);
    }

    for (int kt = 0; kt < K; kt += 16) {
        // store prefetched tile to smem
        As[cA0*4+0][rA0] = pa[0].x; As[cA0*4+1][rA0] = pa[0].y;
        As[cA0*4+2][rA0] = pa[0].z; As[cA0*4+3][rA0] = pa[0].w;
        As[cA1*4+0][rA1] = pa[1].x; As[cA1*4+1][rA1] = pa[1].y;
        As[cA1*4+2][rA1] = pa[1].z; As[cA1*4+3][rA1] = pa[1].w;
        if (!TRANSB) {
            *(float4*)&Bs[rBn0][cBn0 * 4] = pb[0];
            *(float4*)&Bs[rBn1][cBn1 * 4] = pb[1];
        } else {
            Bs[cBt0*4+0][rBt0] = pb[0].x; Bs[cBt0*4+1][rBt0] = pb[0].y;
            Bs[cBt0*4+2][rBt0] = pb[0].z; Bs[cBt0*4+3][rBt0] = pb[0].w;
            Bs[cBt1*4+0][rBt1] = pb[1].x; Bs[cBt1*4+1][rBt1] = pb[1].y;
            Bs[cBt1*4+2][rBt1] = pb[1].z; Bs[cBt1*4+3][rBt1] = pb[1].w;
        }
        __syncthreads();
        // prefetch next tile (overlaps with compute below)
        int kn = kt + 16;
        if (kn < K) {
            pa[0] = *(const float4*)(A + (size_t)(m0 + rA0) * K + kn + cA0 * 4);
            pa[1] = *(const float4*)(A + (size_t)(m0 + rA1) * K + kn + cA1 * 4);
            if (!TRANSB) {
                pb[0] = *(const float4*)(B + (size_t)(kn + rBn0) * N + n0 + cBn0 * 4);
                pb[1] = *(const float4*)(B + (size_t)(kn + rBn1) * N + n0 + cBn1 * 4);
            } else {
                pb[0] = *(const float4*)(B + (size_t)(n0 + rBt0) * K + kn + cBt0 * 4);
                pb[1] = *(const float4*)(B + (size_t)(n0 + rBt1) * K + kn + cBt1 * 4);
            }
        }
#pragma unroll
        for (int k = 0; k < 16; k++) {
            float a[8], bvec[8];
            *(float4*)&a[0]    = *(float4*)&As[k][ty * 8];
            *(float4*)&a[4]    = *(float4*)&As[k][ty * 8 + 4];
            *(float4*)&bvec[0] = *(float4*)&Bs[k][tx * 8];
            *(float4*)&bvec[4] = *(float4*)&Bs[k][tx * 8 + 4];
#pragma unroll
            for (int i = 0; i < 8; i++)
#pragma unroll
                for (int j = 0; j < 8; j++) acc[i][j] += a[i] * bvec[j];
        }
        __syncthreads();
    }
#pragma unroll
    for (int i = 0; i < 8; i++) {
        size_t off = (size_t)(m0 + ty * 8 + i) * N + n0 + tx * 8;
        float4 o0 = make_float4(alpha*acc[i][0], alpha*acc[i][1], alpha*acc[i][2], alpha*acc[i][3]);
        float4 o1 = make_float4(alpha*acc[i][4], alpha*acc[i][5], alpha*acc[i][6], alpha*acc[i][7]);
        if (RES) {
            float4 r0 = *(const float4*)(resp + off);
            float4 r1 = *(const float4*)(resp + off + 4);
            o0.x += r0.x; o0.y += r0.y; o0.z += r0.z; o0.w += r0.w;
            o1.x += r1.x; o1.y += r1.y; o1.z += r1.z; o1.w += r1.w;
        }
        *(float4*)(C + off)     = o0;
        *(float4*)(C + off + 4) = o1;
    }
}

// ---------------- causal flash attention, fp32, 1 thread / query row -----------
__global__ void __launch_bounds__(64) attn_kernel(const float* __restrict__ Q,
                                                  const float* __restrict__ K,
                                                  const float* __restrict__ V,
                                                  float* __restrict__ O) {
    int b = blockIdx.z, h = blockIdx.y, q0 = blockIdx.x * 64;
    int tid = threadIdx.x;
    __shared__ float4 Ks[64 * 16];
    __shared__ float4 Vs[64 * 16];
    int q = q0 + tid;
    const float4* Qr = (const float4*)(Q + ((size_t)(b * SS + q)) * DD + h * DHD);
    float4 qv[16], ov[16];
#pragma unroll
    for (int i = 0; i < 16; i++) { qv[i] = Qr[i]; ov[i] = make_float4(0.f, 0.f, 0.f, 0.f); }
    float m = -1e30f, l = 0.f;
    const float scale = 0.125f;   // 1/sqrt(64)
    for (int j0 = 0; j0 <= q0; j0 += 64) {
        __syncthreads();
        const float4* Kb = (const float4*)(K + ((size_t)(b * SS + j0)) * DD + h * DHD);
        const float4* Vb = (const float4*)(V + ((size_t)(b * SS + j0)) * DD + h * DHD);
#pragma unroll
        for (int i = 0; i < 16; i++) {
            int f = tid + 64 * i;
            int r = f >> 4, c4 = f & 15;
            Ks[f] = Kb[(size_t)r * (DD / 4) + c4];
            Vs[f] = Vb[(size_t)r * (DD / 4) + c4];
        }
        __syncthreads();
        int jend = (j0 == q0) ? tid : 63;
#pragma unroll 1
        for (int j = 0; j <= jend; j++) {
            float s0 = 0.f, s1 = 0.f, s2 = 0.f, s3 = 0.f;
#pragma unroll
            for (int d = 0; d < 16; d++) {
                float4 kk = Ks[j * 16 + d];
                s0 += qv[d].x * kk.x; s1 += qv[d].y * kk.y;
                s2 += qv[d].z * kk.z; s3 += qv[d].w * kk.w;
            }
            float s = ((s0 + s1) + (s2 + s3)) * scale;
            if (s > m) {
                float c = __expf(m - s);
                l *= c;
#pragma unroll
                for (int d = 0; d < 16; d++) {
                    ov[d].x *= c; ov[d].y *= c; ov[d].z *= c; ov[d].w *= c;
                }
                m = s;
            }
            float p = __expf(s - m);
            l += p;
#pragma unroll
            for (int d = 0; d < 16; d++) {
                float4 vv = Vs[j * 16 + d];
                ov[d].x += p * vv.x; ov[d].y += p * vv.y;
                ov[d].z += p * vv.z; ov[d].w += p * vv.w;
            }
        }
    }
    float inv = 1.f / l;
    float4* Or = (float4*)(O + ((size_t)(b * SS + q)) * DD + h * DHD);
#pragma unroll
    for (int i = 0; i < 16; i++) {
        float4 o4 = ov[i];
        o4.x *= inv; o4.y *= inv; o4.z *= inv; o4.w *= inv;
        Or[i] = o4;
    }
}

// ---------------- top-8 over 4096 knowledge scores + gather + residual ---------
__global__ void __launch_bounds__(256) topk_kernel(const float* __restrict__ ms,
                                                   const float* __restrict__ x1,
                                                   const float* __restrict__ KV,
                                                   float* __restrict__ out) {
    int token = blockIdx.x;
    __shared__ float sm[NKK];
    __shared__ float rv[256];
    __shared__ int   ri[256];
    __shared__ float tv[TK];
    __shared__ int   ti[TK];
    __shared__ float w8[TK];
    int tid = threadIdx.x;
    const float* row = ms + (size_t)token * NKK;
    for (int i = tid; i < NKK; i += 256) sm[i] = row[i];
    __syncthreads();
    for (int k = 0; k < TK; k++) {
        float bv = -1e30f; int bi = 0x7fffffff;
        for (int i = tid; i < NKK; i += 256) {
            float v = sm[i];
            if (v > bv || (v == bv && i < bi)) { bv = v; bi = i; }
        }
        rv[tid] = bv; ri[tid] = bi;
        __syncthreads();
        for (int s = 128; s; s >>= 1) {
            if (tid < s) {
                float v2 = rv[tid + s]; int i2 = ri[tid + s];
                if (v2 > rv[tid] || (v2 == rv[tid] && i2 < ri[tid])) {
                    rv[tid] = v2; ri[tid] = i2;
                }
            }
            __syncthreads();
        }
        if (tid == 0) { tv[k] = rv[0]; ti[k] = ri[0]; sm[ri[0]] = -1e30f; }
        __syncthreads();
    }
    if (tid == 0) {
        float mx = tv[0];
        float e[TK], s = 0.f;
        for (int k = 0; k < TK; k++) { e[k] = __expf(tv[k] - mx); s += e[k]; }
        float inv = 1.f / s;
        for (int k = 0; k < TK; k++) w8[k] = e[k] * inv;
    }
    __syncthreads();
    for (int d = tid; d < DD; d += 256) {
        float acc = x1[(size_t)token * DD + d];
#pragma unroll
        for (int k = 0; k < TK; k++) acc += w8[k] * KV[(size_t)ti[k] * DD + d];
        out[(size_t)token * DD + d] = acc;
    }
}

// ---------------- driver --------------------------------------------------------
extern "C" void kernel_launch(void* const* d_in, const int* in_sizes, int n_in,
                              void* d_out, int out_size) {
    const float* x   = (const float*)d_in[0];
    const float* imp = (const float*)d_in[1];
    const float* Wc  = (const float*)d_in[2];
    const float* WQ  = (const float*)d_in[3];
    const float* WK  = (const float*)d_in[4];
    const float* WV  = (const float*)d_in[5];
    const float* Wm  = (const float*)d_in[6];
    const float* CN  = (const float*)d_in[7];
    const float* EP  = (const float*)d_in[8];
    const float* kK  = (const float*)d_in[9];
    const float* kV  = (const float*)d_in[10];
    const float* WO  = (const float*)d_in[11];
    const float* g1  = (const float*)d_in[12];
    const float* b1  = (const float*)d_in[13];
    const float* g2  = (const float*)d_in[14];
    const float* b2  = (const float*)d_in[15];
    float* out = (float*)d_out;

    float *nx, *nx2, *w, *wm, *sc, *mc, *h, *qm, *eq, *ek, *ev;
    float *q, *k, *v, *ao, *x1, *msb;
    cudaGetSymbolAddress((void**)&nx,  g_nx);
    cudaGetSymbolAddress((void**)&nx2, g_nx2);
    cudaGetSymbolAddress((void**)&w,   g_w);
    cudaGetSymbolAddress((void**)&wm,  g_wm);
    cudaGetSymbolAddress((void**)&sc,  g_sc);
    cudaGetSymbolAddress((void**)&mc,  g_mc);
    cudaGetSymbolAddress((void**)&h,   g_h);
    cudaGetSymbolAddress((void**)&qm,  g_qm);
    cudaGetSymbolAddress((void**)&eq,  g_eq);
    cudaGetSymbolAddress((void**)&ek,  g_ek);
    cudaGetSymbolAddress((void**)&ev,  g_ev);
    cudaGetSymbolAddress((void**)&q,   g_q);
    cudaGetSymbolAddress((void**)&k,   g_k);
    cudaGetSymbolAddress((void**)&v,   g_v);
    cudaGetSymbolAddress((void**)&ao,  g_ao);
    cudaGetSymbolAddress((void**)&x1,  g_x1);
    cudaGetSymbolAddress((void**)&msb, g_ms);

    const long SD = (long)SS * DD;   // 2097152
    const long DR = (long)DD * RR;   // 262144
    const long SR = (long)SS * RR;   // 524288
    const long RD = (long)RR * DD;   // 262144
    const long SNK = (long)SS * NKK; // 8388608

    // ---- attention sub-block ----
    ln_kernel<<<BB * SS, 256>>>(x, g1, b1, nx);
    zero_kernel<<<1, 128>>>(w, 4 * BB * NEXP);
    zero_kernel<<<1, 32>>>(wm, BB * NEXP);
    route_kernel<<<BB * SS, 128>>>(nx, imp, Wc, WQ, WK, WV, 4, w);
    norm_kernel<<<1, 32>>>(w, 4 * BB);
    mix_kernel<<<(BB * DD * RR) / 256, 256>>>(w, CN, sc);
    mix3_kernel<<<(BB * RR * DD) / 256, 256>>>(w + 1 * BB * NEXP, w + 2 * BB * NEXP,
                                               w + 3 * BB * NEXP, EP, eq, ek, ev);
    // h = nx @ sc : [2048 x 1024] @ [1024 x 256]
    sgemm_kernel<false, false><<<dim3(RR / 128, SS / 128, BB), 256>>>(
        nx, sc, nullptr, h, SS, RR, DD, 1.f, SD, DR, SR, 0);
    // Q/K/V = h @ e : [2048 x 256] @ [256 x 1024]
    sgemm_kernel<false, false><<<dim3(DD / 128, SS / 128, BB), 256>>>(
        h, eq, nullptr, q, SS, DD, RR, 1.f, SR, RD, SD, 0);
    sgemm_kernel<false, false><<<dim3(DD / 128, SS / 128, BB), 256>>>(
        h, ek, nullptr, k, SS, DD, RR, 1.f, SR, RD, SD, 0);
    sgemm_kernel<false, false><<<dim3(DD / 128, SS / 128, BB), 256>>>(
        h, ev, nullptr, v, SS, DD, RR, 1.f, SR, RD, SD, 0);
    attn_kernel<<<dim3(SS / 64, HH, BB), 64>>>(q, k, v, ao);
    // x1 = x + ao @ WO^T : [4096 x 1024] @ [1024 x 1024]^T
    sgemm_kernel<true, true><<<dim3(DD / 128, (BB * SS) / 128, 1), 256>>>(
        ao, WO, x, x1, BB * SS, DD, DD, 1.f, 0, 0, 0, 0);

    // ---- memory sub-block ----
    ln_kernel<<<BB * SS, 256>>>(x1, g2, b2, nx2);
    route_kernel<<<BB * SS, 128>>>(nx2, imp, Wm, Wm, Wm, Wm, 1, wm);
    norm_kernel<<<1, 32>>>(wm, BB);
    mix_kernel<<<(BB * DD * RR) / 256, 256>>>(wm, CN, mc);
    // Qm = nx2 @ mc
    sgemm_kernel<false, false><<<dim3(RR / 128, SS / 128, BB), 256>>>(
        nx2, mc, nullptr, qm, SS, RR, DD, 1.f, SD, DR, SR, 0);
    // ms = Qm @ kK^T / sqrt(256)
    sgemm_kernel<true, false><<<dim3(NKK / 128, SS / 128, BB), 256>>>(
        qm, kK, nullptr, msb, SS, NKK, RR, 0.0625f, SR, 0, SNK, 0);
    topk_kernel<<<BB * SS, 256>>>(msb, x1, kV, out);
}

// round 5
// speedup vs baseline: 1.3690x; 1.3690x over previous
#include <cuda_runtime.h>
#include <math.h>
#include <stdint.h>

#define BB 2
#define SS 2048
#define DD 1024
#define HH 16
#define DHD 64
#define RR 256
#define NEXP 16
#define NKK 4096
#define TK 8

// ---------------- scratch (device globals; no allocation allowed) -------------
__device__ float g_nx [BB*SS*DD];
__device__ float g_nx2[BB*SS*DD];
__device__ float g_w  [4*BB*NEXP];
__device__ float g_wm [BB*NEXP];
__device__ float g_sc [BB*DD*RR];
__device__ float g_mc [BB*DD*RR];
__device__ float g_h  [BB*SS*RR];
__device__ float g_qm [BB*SS*RR];
__device__ float g_eq [BB*RR*DD];
__device__ float g_ek [BB*RR*DD];
__device__ float g_ev [BB*RR*DD];
__device__ float g_q  [BB*SS*DD];
__device__ float g_k  [BB*SS*DD];
__device__ float g_v  [BB*SS*DD];
__device__ float g_ao [BB*SS*DD];
__device__ float g_x1 [BB*SS*DD];
__device__ float g_ms [(size_t)BB*SS*NKK];

// ---------------- utility ------------------------------------------------------
__global__ void zero_kernel(float* p, int n) {
    int i = blockIdx.x * blockDim.x + threadIdx.x;
    if (i < n) p[i] = 0.f;
}

__device__ __forceinline__ float tf32r(float x) {
    uint32_t u;
    asm("cvt.rna.tf32.f32 %0, %1;" : "=r"(u) : "f"(x));
    return __uint_as_float(u);
}

__device__ __forceinline__ void sts4_tf32(float* p, float4 v) {
    float4 o;
    o.x = tf32r(v.x); o.y = tf32r(v.y); o.z = tf32r(v.z); o.w = tf32r(v.w);
    *(float4*)p = o;
}

__device__ __forceinline__ void mma8(float* c, const float* a, const float* b) {
    uint32_t A0 = __float_as_uint(a[0]), A1 = __float_as_uint(a[1]);
    uint32_t A2 = __float_as_uint(a[2]), A3 = __float_as_uint(a[3]);
    uint32_t B0 = __float_as_uint(b[0]), B1 = __float_as_uint(b[1]);
    asm volatile(
        "mma.sync.aligned.m16n8k8.row.col.f32.tf32.tf32.f32 "
        "{%0,%1,%2,%3}, {%4,%5,%6,%7}, {%8,%9}, {%0,%1,%2,%3};\n"
        : "+f"(c[0]), "+f"(c[1]), "+f"(c[2]), "+f"(c[3])
        : "r"(A0), "r"(A1), "r"(A2), "r"(A3), "r"(B0), "r"(B1));
}

// ---------------- LayerNorm: one block per row, 256 threads --------------------
__global__ void __launch_bounds__(256) ln_kernel(const float* __restrict__ x,
                                                 const float* __restrict__ g,
                                                 const float* __restrict__ b,
                                                 float* __restrict__ out) {
    int row = blockIdx.x;
    const float4* xr = (const float4*)(x + (size_t)row * DD);
    float4 t = xr[threadIdx.x];
    float s  = t.x + t.y + t.z + t.w;
    float sq = t.x*t.x + t.y*t.y + t.z*t.z + t.w*t.w;
    __shared__ float rs[8], rq[8];
    for (int o = 16; o; o >>= 1) {
        s  += __shfl_down_sync(0xffffffffu, s,  o);
        sq += __shfl_down_sync(0xffffffffu, sq, o);
    }
    int wid = threadIdx.x >> 5, lane = threadIdx.x & 31;
    if (lane == 0) { rs[wid] = s; rq[wid] = sq; }
    __syncthreads();
    if (threadIdx.x == 0) {
        float a = 0.f, c = 0.f;
        for (int i = 0; i < 8; i++) { a += rs[i]; c += rq[i]; }
        rs[0] = a; rq[0] = c;
    }
    __syncthreads();
    float mean = rs[0] * (1.f / DD);
    float var  = rq[0] * (1.f / DD) - mean * mean;
    float rstd = rsqrtf(var + 1e-5f);
    float4 gg = ((const float4*)g)[threadIdx.x];
    float4 bb = ((const float4*)b)[threadIdx.x];
    float4 o4;
    o4.x = (t.x - mean) * rstd * gg.x + bb.x;
    o4.y = (t.y - mean) * rstd * gg.y + bb.y;
    o4.z = (t.z - mean) * rstd * gg.z + bb.z;
    o4.w = (t.w - mean) * rstd * gg.w + bb.w;
    ((float4*)(out + (size_t)row * DD))[threadIdx.x] = o4;
}

// ---------------- routing v2: 16 tokens/block, W tiled through smem ------------
// logits[t][e] for e = r*16+n over nW routers; per-token softmax per router,
// importance-weighted pooled into wacc[(r*BB+b)*16+n] via atomics.
__global__ void __launch_bounds__(256) route2_kernel(
    const float* __restrict__ nx, const float* __restrict__ imp,
    const float* __restrict__ W0, const float* __restrict__ W1,
    const float* __restrict__ W2, const float* __restrict__ W3,
    int nW, float* __restrict__ wacc) {
    __shared__ float xs[16 * 132];
    __shared__ float ws[64 * 132];
    __shared__ float lg[16 * 64];
    int tid = threadIdx.x;
    int tok0 = blockIdx.x * 16;
    int t = tid & 15, eg = tid >> 4;      // thread computes e = eg*4 .. eg*4+3
    int nE = nW * NEXP;
    const float* Ws[4] = {W0, W1, W2, W3};
    float a0 = 0.f, a1 = 0.f, a2 = 0.f, a3 = 0.f;
    for (int c = 0; c < DD / 128; c++) {
        __syncthreads();
        // stage x chunk: 16 tokens x 128
#pragma unroll
        for (int i = 0; i < 2; i++) {
            int f = tid + 256 * i;
            int tt = f >> 5, d4 = f & 31;
            *(float4*)&xs[tt * 132 + d4 * 4] =
                *(const float4*)(nx + (size_t)(tok0 + tt) * DD + c * 128 + d4 * 4);
        }
        // stage W chunk: nE x 128
#pragma unroll
        for (int i = 0; i < 8; i++) {
            int f = tid + 256 * i;
            if (f < nE * 32) {
                int e = f >> 5, d4 = f & 31;
                const float* src = Ws[e >> 4] + (size_t)(e & 15) * DD + c * 128 + d4 * 4;
                *(float4*)&ws[e * 132 + d4 * 4] = *(const float4*)src;
            }
        }
        __syncthreads();
        if (eg * 4 < nE) {
#pragma unroll 4
            for (int d4 = 0; d4 < 32; d4++) {
                float4 xv = *(float4*)&xs[t * 132 + d4 * 4];
                float4 w0 = *(float4*)&ws[(eg * 4 + 0) * 132 + d4 * 4];
                float4 w1 = *(float4*)&ws[(eg * 4 + 1) * 132 + d4 * 4];
                float4 w2 = *(float4*)&ws[(eg * 4 + 2) * 132 + d4 * 4];
                float4 w3 = *(float4*)&ws[(eg * 4 + 3) * 132 + d4 * 4];
                a0 += xv.x*w0.x + xv.y*w0.y + xv.z*w0.z + xv.w*w0.w;
                a1 += xv.x*w1.x + xv.y*w1.y + xv.z*w1.z + xv.w*w1.w;
                a2 += xv.x*w2.x + xv.y*w2.y + xv.z*w2.z + xv.w*w2.w;
                a3 += xv.x*w3.x + xv.y*w3.y + xv.z*w3.z + xv.w*w3.w;
            }
        }
    }
    if (eg * 4 < nE) {
        lg[t * 64 + eg * 4 + 0] = a0;
        lg[t * 64 + eg * 4 + 1] = a1;
        lg[t * 64 + eg * 4 + 2] = a2;
        lg[t * 64 + eg * 4 + 3] = a3;
    }
    __syncthreads();
    // pool: one thread per (token, router)
    if (tid < 16 * nW) {
        int tt = tid & 15, r = tid >> 4;
        int tok = tok0 + tt, b = tok / SS;
        float mx = -1e30f;
        for (int n = 0; n < NEXP; n++) mx = fmaxf(mx, lg[tt * 64 + r * 16 + n]);
        float e[NEXP], sum = 0.f;
        for (int n = 0; n < NEXP; n++) {
            e[n] = __expf(lg[tt * 64 + r * 16 + n] - mx);
            sum += e[n];
        }
        float wgt = imp[tok] / sum;
        for (int n = 0; n < NEXP; n++)
            atomicAdd(&wacc[(r * BB + b) * NEXP + n], e[n] * wgt);
    }
}

__global__ void norm_kernel(float* w, int cnt) {
    int i = threadIdx.x;
    if (i < cnt) {
        float* p = w + i * NEXP;
        float s = 0.f;
        for (int n = 0; n < NEXP; n++) s += p[n];
        float inv = 1.f / (s + 1e-8f);
        for (int n = 0; n < NEXP; n++) p[n] *= inv;
    }
}

// ---------------- pool mixes: out[b, r] = sum_n w[b,n] * P[n, r] ---------------
__global__ void __launch_bounds__(256) mix_kernel(const float* __restrict__ w,
                                                  const float* __restrict__ P,
                                                  float* __restrict__ out) {
    const size_t X = (size_t)DD * RR;
    size_t idx = (size_t)blockIdx.x * 256 + threadIdx.x;
    int b = (int)(idx / X);
    size_t r = idx % X;
    float acc = 0.f;
#pragma unroll
    for (int n = 0; n < NEXP; n++) acc += w[b * NEXP + n] * P[(size_t)n * X + r];
    out[idx] = acc;
}

__global__ void __launch_bounds__(256) mix3_kernel(
    const float* __restrict__ wq, const float* __restrict__ wk,
    const float* __restrict__ wv, const float* __restrict__ P,
    float* __restrict__ eq, float* __restrict__ ek, float* __restrict__ ev) {
    const size_t X = (size_t)RR * DD;
    size_t idx = (size_t)blockIdx.x * 256 + threadIdx.x;
    int b = (int)(idx / X);
    size_t r = idx % X;
    float aq = 0.f, ak = 0.f, av = 0.f;
#pragma unroll
    for (int n = 0; n < NEXP; n++) {
        float p = P[(size_t)n * X + r];
        aq += wq[b * NEXP + n] * p;
        ak += wk[b * NEXP + n] * p;
        av += wv[b * NEXP + n] * p;
    }
    eq[idx] = aq; ek[idx] = ak; ev[idx] = av;
}

// ---------------- tf32 tensor-core GEMM: 128x128 block, BK=16 ------------------
// 256 threads = 8 warps (2 x 4), warp tile 64x32, mma.m16n8k8 tf32.
// Inputs rounded to tf32 at smem staging (cvt.rna), fp32 accumulate.
// TRANSB=false: B[K,N]. TRANSB=true: B[N,K]. C = alpha*A*B (+res).
template<bool TRANSB, bool RES>
__global__ void __launch_bounds__(256, 2) tgemm_kernel(
    const float* __restrict__ A, const float* __restrict__ B,
    const float* __restrict__ resp, float* __restrict__ C,
    int M, int N, int K, float alpha,
    long sA, long sB, long sC, long sR) {
    A += (size_t)blockIdx.z * sA;
    B += (size_t)blockIdx.z * sB;
    C += (size_t)blockIdx.z * sC;
    if (RES) resp += (size_t)blockIdx.z * sR;
    const int n0 = blockIdx.x * 128, m0 = blockIdx.y * 128;
    __shared__ float As[128 * 20];        // [m][k], stride 20 -> conflict-free frags
    __shared__ float Bs[2560];            // NN: [k][136] (2176) ; NT: [n][20] (2560)
    int tid = threadIdx.x;
    int lane = tid & 31, w = tid >> 5;
    int wm = (w & 1) * 64, wn = (w >> 1) * 32;
    int lq = lane >> 2, lr = lane & 3;

    // staging coordinates
    int rowA = tid >> 2, c4A = (tid & 3) * 4;
    const float* gA = A + (size_t)(m0 + rowA) * K + c4A;
    float* sAp = &As[rowA * 20 + c4A];
    const float* gB;
    float* sBp;
    int gBstep, gBoff2, sBoff2;
    if (!TRANSB) {
        int rB = tid >> 5, cB = (tid & 31) * 4;
        gB = B + (size_t)rB * N + n0 + cB;
        sBp = &Bs[rB * 136 + cB];
        gBstep = 16 * N; gBoff2 = 8 * N; sBoff2 = 8 * 136;
    } else {
        int nB = tid >> 2, c4B = (tid & 3) * 4;
        gB = B + (size_t)(n0 + nB) * K + c4B;
        sBp = &Bs[nB * 20 + c4B];
        gBstep = 16; gBoff2 = 64 * K; sBoff2 = 64 * 20;
    }

    float acc[4][4][4];
#pragma unroll
    for (int mt = 0; mt < 4; mt++)
#pragma unroll
        for (int nt = 0; nt < 4; nt++)
#pragma unroll
            for (int i = 0; i < 4; i++) acc[mt][nt][i] = 0.f;

    float4 pa0 = *(const float4*)gA;
    float4 pa1 = *(const float4*)(gA + (size_t)64 * K);
    float4 pb0 = *(const float4*)gB;
    float4 pb1 = *(const float4*)(gB + gBoff2);

    for (int kt = 0; kt < K; kt += 16) {
        sts4_tf32(sAp, pa0);
        sts4_tf32(sAp + 64 * 20, pa1);
        sts4_tf32(sBp, pb0);
        sts4_tf32(sBp + sBoff2, pb1);
        __syncthreads();
        if (kt + 16 < K) {
            gA += 16;
            pa0 = *(const float4*)gA;
            pa1 = *(const float4*)(gA + (size_t)64 * K);
            gB += gBstep;
            pb0 = *(const float4*)gB;
            pb1 = *(const float4*)(gB + gBoff2);
        }
#pragma unroll
        for (int ks = 0; ks < 16; ks += 8) {
            float af[4][4], bf[4][2];
#pragma unroll
            for (int mt = 0; mt < 4; mt++) {
                int r = wm + mt * 16 + lq;
                af[mt][0] = As[r * 20 + ks + lr];
                af[mt][1] = As[(r + 8) * 20 + ks + lr];
                af[mt][2] = As[r * 20 + ks + lr + 4];
                af[mt][3] = As[(r + 8) * 20 + ks + lr + 4];
            }
#pragma unroll
            for (int nt = 0; nt < 4; nt++) {
                int cc = wn + nt * 8 + lq;
                if (!TRANSB) {
                    bf[nt][0] = Bs[(ks + lr) * 136 + cc];
                    bf[nt][1] = Bs[(ks + 4 + lr) * 136 + cc];
                } else {
                    bf[nt][0] = Bs[cc * 20 + ks + lr];
                    bf[nt][1] = Bs[cc * 20 + ks + 4 + lr];
                }
            }
#pragma unroll
            for (int mt = 0; mt < 4; mt++)
#pragma unroll
                for (int nt = 0; nt < 4; nt++)
                    mma8(acc[mt][nt], af[mt], bf[nt]);
        }
        __syncthreads();
    }
    // epilogue
#pragma unroll
    for (int mt = 0; mt < 4; mt++) {
        int r = m0 + wm + mt * 16 + lq;
#pragma unroll
        for (int nt = 0; nt < 4; nt++) {
            int cc = n0 + wn + nt * 8 + 2 * lr;
            float2 v0 = make_float2(alpha * acc[mt][nt][0], alpha * acc[mt][nt][1]);
            float2 v1 = make_float2(alpha * acc[mt][nt][2], alpha * acc[mt][nt][3]);
            size_t o0 = (size_t)r * N + cc;
            size_t o1 = (size_t)(r + 8) * N + cc;
            if (RES) {
                float2 r0 = *(const float2*)(resp + o0);
                float2 r1 = *(const float2*)(resp + o1);
                v0.x += r0.x; v0.y += r0.y;
                v1.x += r1.x; v1.y += r1.y;
            }
            *(float2*)(C + o0) = v0;
            *(float2*)(C + o1) = v1;
        }
    }
}

// ---------------- causal flash attention, fp32, 1 thread / query row -----------
__global__ void __launch_bounds__(64) attn_kernel(const float* __restrict__ Q,
                                                  const float* __restrict__ K,
                                                  const float* __restrict__ V,
                                                  float* __restrict__ O) {
    int b = blockIdx.z, h = blockIdx.y, q0 = blockIdx.x * 64;
    int tid = threadIdx.x;
    __shared__ float4 Ks[64 * 16];
    __shared__ float4 Vs[64 * 16];
    int q = q0 + tid;
    const float4* Qr = (const float4*)(Q + ((size_t)(b * SS + q)) * DD + h * DHD);
    float4 qv[16], ov[16];
#pragma unroll
    for (int i = 0; i < 16; i++) { qv[i] = Qr[i]; ov[i] = make_float4(0.f, 0.f, 0.f, 0.f); }
    float m = -1e30f, l = 0.f;
    const float scale = 0.125f;   // 1/sqrt(64)
    for (int j0 = 0; j0 <= q0; j0 += 64) {
        __syncthreads();
        const float4* Kb = (const float4*)(K + ((size_t)(b * SS + j0)) * DD + h * DHD);
        const float4* Vb = (const float4*)(V + ((size_t)(b * SS + j0)) * DD + h * DHD);
#pragma unroll
        for (int i = 0; i < 16; i++) {
            int f = tid + 64 * i;
            int r = f >> 4, c4 = f & 15;
            Ks[f] = Kb[(size_t)r * (DD / 4) + c4];
            Vs[f] = Vb[(size_t)r * (DD / 4) + c4];
        }
        __syncthreads();
        int jend = (j0 == q0) ? tid : 63;
#pragma unroll 1
        for (int j = 0; j <= jend; j++) {
            float s0 = 0.f, s1 = 0.f, s2 = 0.f, s3 = 0.f;
#pragma unroll
            for (int d = 0; d < 16; d++) {
                float4 kk = Ks[j * 16 + d];
                s0 += qv[d].x * kk.x; s1 += qv[d].y * kk.y;
                s2 += qv[d].z * kk.z; s3 += qv[d].w * kk.w;
            }
            float s = ((s0 + s1) + (s2 + s3)) * scale;
            if (s > m) {
                float c = __expf(m - s);
                l *= c;
#pragma unroll
                for (int d = 0; d < 16; d++) {
                    ov[d].x *= c; ov[d].y *= c; ov[d].z *= c; ov[d].w *= c;
                }
                m = s;
            }
            float p = __expf(s - m);
            l += p;
#pragma unroll
            for (int d = 0; d < 16; d++) {
                float4 vv = Vs[j * 16 + d];
                ov[d].x += p * vv.x; ov[d].y += p * vv.y;
                ov[d].z += p * vv.z; ov[d].w += p * vv.w;
            }
        }
    }
    float inv = 1.f / l;
    float4* Or = (float4*)(O + ((size_t)(b * SS + q)) * DD + h * DHD);
#pragma unroll
    for (int i = 0; i < 16; i++) {
        float4 o4 = ov[i];
        o4.x *= inv; o4.y *= inv; o4.z *= inv; o4.w *= inv;
        Or[i] = o4;
    }
}

// ---------------- top-8 over 4096 knowledge scores + gather + residual ---------
__global__ void __launch_bounds__(256) topk_kernel(const float* __restrict__ ms,
                                                   const float* __restrict__ x1,
                                                   const float* __restrict__ KV,
                                                   float* __restrict__ out) {
    int token = blockIdx.x;
    __shared__ float sm[NKK];
    __shared__ float rv[256];
    __shared__ int   ri[256];
    __shared__ float tv[TK];
    __shared__ int   ti[TK];
    __shared__ float w8[TK];
    int tid = threadIdx.x;
    const float* row = ms + (size_t)token * NKK;
    for (int i = tid; i < NKK; i += 256) sm[i] = row[i];
    __syncthreads();
    for (int k = 0; k < TK; k++) {
        float bv = -1e30f; int bi = 0x7fffffff;
        for (int i = tid; i < NKK; i += 256) {
            float v = sm[i];
            if (v > bv || (v == bv && i < bi)) { bv = v; bi = i; }
        }
        rv[tid] = bv; ri[tid] = bi;
        __syncthreads();
        for (int s = 128; s; s >>= 1) {
            if (tid < s) {
                float v2 = rv[tid + s]; int i2 = ri[tid + s];
                if (v2 > rv[tid] || (v2 == rv[tid] && i2 < ri[tid])) {
                    rv[tid] = v2; ri[tid] = i2;
                }
            }
            __syncthreads();
        }
        if (tid == 0) { tv[k] = rv[0]; ti[k] = ri[0]; sm[ri[0]] = -1e30f; }
        __syncthreads();
    }
    if (tid == 0) {
        float mx = tv[0];
        float e[TK], s = 0.f;
        for (int k = 0; k < TK; k++) { e[k] = __expf(tv[k] - mx); s += e[k]; }
        float inv = 1.f / s;
        for (int k = 0; k < TK; k++) w8[k] = e[k] * inv;
    }
    __syncthreads();
    for (int d = tid; d < DD; d += 256) {
        float acc = x1[(size_t)token * DD + d];
#pragma unroll
        for (int k = 0; k < TK; k++) acc += w8[k] * KV[(size_t)ti[k] * DD + d];
        out[(size_t)token * DD + d] = acc;
    }
}

// ---------------- driver --------------------------------------------------------
extern "C" void kernel_launch(void* const* d_in, const int* in_sizes, int n_in,
                              void* d_out, int out_size) {
    const float* x   = (const float*)d_in[0];
    const float* imp = (const float*)d_in[1];
    const float* Wc  = (const float*)d_in[2];
    const float* WQ  = (const float*)d_in[3];
    const float* WK  = (const float*)d_in[4];
    const float* WV  = (const float*)d_in[5];
    const float* Wm  = (const float*)d_in[6];
    const float* CN  = (const float*)d_in[7];
    const float* EP  = (const float*)d_in[8];
    const float* kK  = (const float*)d_in[9];
    const float* kV  = (const float*)d_in[10];
    const float* WO  = (const float*)d_in[11];
    const float* g1  = (const float*)d_in[12];
    const float* b1  = (const float*)d_in[13];
    const float* g2  = (const float*)d_in[14];
    const float* b2  = (const float*)d_in[15];
    float* out = (float*)d_out;

    float *nx, *nx2, *w, *wm, *sc, *mc, *h, *qm, *eq, *ek, *ev;
    float *q, *k, *v, *ao, *x1, *msb;
    cudaGetSymbolAddress((void**)&nx,  g_nx);
    cudaGetSymbolAddress((void**)&nx2, g_nx2);
    cudaGetSymbolAddress((void**)&w,   g_w);
    cudaGetSymbolAddress((void**)&wm,  g_wm);
    cudaGetSymbolAddress((void**)&sc,  g_sc);
    cudaGetSymbolAddress((void**)&mc,  g_mc);
    cudaGetSymbolAddress((void**)&h,   g_h);
    cudaGetSymbolAddress((void**)&qm,  g_qm);
    cudaGetSymbolAddress((void**)&eq,  g_eq);
    cudaGetSymbolAddress((void**)&ek,  g_ek);
    cudaGetSymbolAddress((void**)&ev,  g_ev);
    cudaGetSymbolAddress((void**)&q,   g_q);
    cudaGetSymbolAddress((void**)&k,   g_k);
    cudaGetSymbolAddress((void**)&v,   g_v);
    cudaGetSymbolAddress((void**)&ao,  g_ao);
    cudaGetSymbolAddress((void**)&x1,  g_x1);
    cudaGetSymbolAddress((void**)&msb, g_ms);

    const long SD = (long)SS * DD;   // 2097152
    const long DR = (long)DD * RR;   // 262144
    const long SR = (long)SS * RR;   // 524288
    const long RD = (long)RR * DD;   // 262144
    const long SNK = (long)SS * NKK; // 8388608

    // ---- attention sub-block ----
    ln_kernel<<<BB * SS, 256>>>(x, g1, b1, nx);
    zero_kernel<<<1, 128>>>(w, 4 * BB * NEXP);
    zero_kernel<<<1, 32>>>(wm, BB * NEXP);
    route2_kernel<<<BB * SS / 16, 256>>>(nx, imp, Wc, WQ, WK, WV, 4, w);
    norm_kernel<<<1, 32>>>(w, 4 * BB);
    mix_kernel<<<(BB * DD * RR) / 256, 256>>>(w, CN, sc);
    mix3_kernel<<<(BB * RR * DD) / 256, 256>>>(w + 1 * BB * NEXP, w + 2 * BB * NEXP,
                                               w + 3 * BB * NEXP, EP, eq, ek, ev);
    // h = nx @ sc : [2048 x 1024] @ [1024 x 256]
    tgemm_kernel<false, false><<<dim3(RR / 128, SS / 128, BB), 256>>>(
        nx, sc, nullptr, h, SS, RR, DD, 1.f, SD, DR, SR, 0);
    // Q/K/V = h @ e : [2048 x 256] @ [256 x 1024]
    tgemm_kernel<false, false><<<dim3(DD / 128, SS / 128, BB), 256>>>(
        h, eq, nullptr, q, SS, DD, RR, 1.f, SR, RD, SD, 0);
    tgemm_kernel<false, false><<<dim3(DD / 128, SS / 128, BB), 256>>>(
        h, ek, nullptr, k, SS, DD, RR, 1.f, SR, RD, SD, 0);
    tgemm_kernel<false, false><<<dim3(DD / 128, SS / 128, BB), 256>>>(
        h, ev, nullptr, v, SS, DD, RR, 1.f, SR, RD, SD, 0);
    attn_kernel<<<dim3(SS / 64, HH, BB), 64>>>(q, k, v, ao);
    // x1 = x + ao @ WO^T : [4096 x 1024] @ [1024 x 1024]^T
    tgemm_kernel<true, true><<<dim3(DD / 128, (BB * SS) / 128, 1), 256>>>(
        ao, WO, x, x1, BB * SS, DD, DD, 1.f, 0, 0, 0, 0);

    // ---- memory sub-block ----
    ln_kernel<<<BB * SS, 256>>>(x1, g2, b2, nx2);
    route2_kernel<<<BB * SS / 16, 256>>>(nx2, imp, Wm, Wm, Wm, Wm, 1, wm);
    norm_kernel<<<1, 32>>>(wm, BB);
    mix_kernel<<<(BB * DD * RR) / 256, 256>>>(wm, CN, mc);
    // Qm = nx2 @ mc
    tgemm_kernel<false, false><<<dim3(RR / 128, SS / 128, BB), 256>>>(
        nx2, mc, nullptr, qm, SS, RR, DD, 1.f, SD, DR, SR, 0);
    // ms = Qm @ kK^T / sqrt(256)
    tgemm_kernel<true, false><<<dim3(NKK / 128, SS / 128, BB), 256>>>(
        qm, kK, nullptr, msb, SS, NKK, RR, 0.0625f, SR, 0, SNK, 0);
    topk_kernel<<<BB * SS, 256>>>(msb, x1, kV, out);
}

// round 6
// speedup vs baseline: 3.0040x; 2.1944x over previous
#include <cuda_runtime.h>
#include <math.h>
#include <stdint.h>

#define BB 2
#define SS 2048
#define DD 1024
#define HH 16
#define DHD 64
#define RR 256
#define NEXP 16
#define NKK 4096
#define TK 8
#define TT (BB*SS)

// ---------------- scratch (device globals; no allocation allowed) -------------
__device__ float g_nx [BB*SS*DD];
__device__ float g_nx2[BB*SS*DD];
__device__ float g_w  [4*BB*NEXP];
__device__ float g_wm [BB*NEXP];
__device__ float g_sc [BB*DD*RR];
__device__ float g_mc [BB*DD*RR];
__device__ float g_h  [BB*SS*RR];
__device__ float g_qm [BB*SS*RR];
__device__ float g_eq [BB*RR*DD];
__device__ float g_ek [BB*RR*DD];
__device__ float g_ev [BB*RR*DD];
__device__ float g_q  [BB*SS*DD];
__device__ float g_k  [BB*SS*DD];
__device__ float g_v  [BB*SS*DD];
__device__ float g_ao [BB*SS*DD];
__device__ float g_x1 [BB*SS*DD];
__device__ float g_ms [(size_t)BB*SS*NKK];
__device__ float g_lgp[(size_t)8*TT*64];

// ---------------- utility ------------------------------------------------------
__global__ void zero_kernel(float* p, int n) {
    int i = blockIdx.x * blockDim.x + threadIdx.x;
    if (i < n) p[i] = 0.f;
}

__device__ __forceinline__ float tf32r(float x) {
    uint32_t u;
    asm("cvt.rna.tf32.f32 %0, %1;" : "=r"(u) : "f"(x));
    return __uint_as_float(u);
}

__device__ __forceinline__ void sts4_tf32(float* p, float4 v) {
    float4 o;
    o.x = tf32r(v.x); o.y = tf32r(v.y); o.z = tf32r(v.z); o.w = tf32r(v.w);
    *(float4*)p = o;
}

__device__ __forceinline__ void mma8(float* c, const float* a, const float* b) {
    uint32_t A0 = __float_as_uint(a[0]), A1 = __float_as_uint(a[1]);
    uint32_t A2 = __float_as_uint(a[2]), A3 = __float_as_uint(a[3]);
    uint32_t B0 = __float_as_uint(b[0]), B1 = __float_as_uint(b[1]);
    asm volatile(
        "mma.sync.aligned.m16n8k8.row.col.f32.tf32.tf32.f32 "
        "{%0,%1,%2,%3}, {%4,%5,%6,%7}, {%8,%9}, {%0,%1,%2,%3};\n"
        : "+f"(c[0]), "+f"(c[1]), "+f"(c[2]), "+f"(c[3])
        : "r"(A0), "r"(A1), "r"(A2), "r"(A3), "r"(B0), "r"(B1));
}

// ---------------- LayerNorm: one block per row, 256 threads --------------------
__global__ void __launch_bounds__(256) ln_kernel(const float* __restrict__ x,
                                                 const float* __restrict__ g,
                                                 const float* __restrict__ b,
                                                 float* __restrict__ out) {
    int row = blockIdx.x;
    const float4* xr = (const float4*)(x + (size_t)row * DD);
    float4 t = xr[threadIdx.x];
    float s  = t.x + t.y + t.z + t.w;
    float sq = t.x*t.x + t.y*t.y + t.z*t.z + t.w*t.w;
    __shared__ float rs[8], rq[8];
    for (int o = 16; o; o >>= 1) {
        s  += __shfl_down_sync(0xffffffffu, s,  o);
        sq += __shfl_down_sync(0xffffffffu, sq, o);
    }
    int wid = threadIdx.x >> 5, lane = threadIdx.x & 31;
    if (lane == 0) { rs[wid] = s; rq[wid] = sq; }
    __syncthreads();
    if (threadIdx.x == 0) {
        float a = 0.f, c = 0.f;
        for (int i = 0; i < 8; i++) { a += rs[i]; c += rq[i]; }
        rs[0] = a; rq[0] = c;
    }
    __syncthreads();
    float mean = rs[0] * (1.f / DD);
    float var  = rq[0] * (1.f / DD) - mean * mean;
    float rstd = rsqrtf(var + 1e-5f);
    float4 gg = ((const float4*)g)[threadIdx.x];
    float4 bb = ((const float4*)b)[threadIdx.x];
    float4 o4;
    o4.x = (t.x - mean) * rstd * gg.x + bb.x;
    o4.y = (t.y - mean) * rstd * gg.y + bb.y;
    o4.z = (t.z - mean) * rstd * gg.z + bb.z;
    o4.w = (t.w - mean) * rstd * gg.w + bb.w;
    ((float4*)(out + (size_t)row * DD))[threadIdx.x] = o4;
}

// ---------------- routing v3: partial logits over D-chunks ---------------------
// grid (TT/16, 8): block computes logits for 16 tokens x nE experts over a
// 128-wide D slice; writes partials to lgp[chunk][token][64] (no atomics).
__global__ void __launch_bounds__(256) route3_kernel(
    const float* __restrict__ nx,
    const float* __restrict__ W0, const float* __restrict__ W1,
    const float* __restrict__ W2, const float* __restrict__ W3,
    int nE, float* __restrict__ lgp) {
    __shared__ float xs[16 * 132];
    __shared__ float ws[64 * 132];
    int tid = threadIdx.x;
    int tok0 = blockIdx.x * 16;
    int c = blockIdx.y;
    int t = tid & 15, eg = tid >> 4;
    const float* Ws[4] = {W0, W1, W2, W3};
#pragma unroll
    for (int i = 0; i < 2; i++) {
        int f = tid + 256 * i;
        int tt = f >> 5, d4 = f & 31;
        *(float4*)&xs[tt * 132 + d4 * 4] =
            *(const float4*)(nx + (size_t)(tok0 + tt) * DD + c * 128 + d4 * 4);
    }
#pragma unroll
    for (int i = 0; i < 8; i++) {
        int f = tid + 256 * i;
        if (f < nE * 32) {
            int e = f >> 5, d4 = f & 31;
            const float* src = Ws[e >> 4] + (size_t)(e & 15) * DD + c * 128 + d4 * 4;
            *(float4*)&ws[e * 132 + d4 * 4] = *(const float4*)src;
        }
    }
    __syncthreads();
    if (eg * 4 < nE) {
        float a0 = 0.f, a1 = 0.f, a2 = 0.f, a3 = 0.f;
#pragma unroll 4
        for (int d4 = 0; d4 < 32; d4++) {
            float4 xv = *(float4*)&xs[t * 132 + d4 * 4];
            float4 w0 = *(float4*)&ws[(eg * 4 + 0) * 132 + d4 * 4];
            float4 w1 = *(float4*)&ws[(eg * 4 + 1) * 132 + d4 * 4];
            float4 w2 = *(float4*)&ws[(eg * 4 + 2) * 132 + d4 * 4];
            float4 w3 = *(float4*)&ws[(eg * 4 + 3) * 132 + d4 * 4];
            a0 += xv.x*w0.x + xv.y*w0.y + xv.z*w0.z + xv.w*w0.w;
            a1 += xv.x*w1.x + xv.y*w1.y + xv.z*w1.z + xv.w*w1.w;
            a2 += xv.x*w2.x + xv.y*w2.y + xv.z*w2.z + xv.w*w2.w;
            a3 += xv.x*w3.x + xv.y*w3.y + xv.z*w3.z + xv.w*w3.w;
        }
        *(float4*)&lgp[((size_t)c * TT + tok0 + t) * 64 + eg * 4] =
            make_float4(a0, a1, a2, a3);
    }
}

// pool partials: sum 8 chunks, softmax within 16-expert router segments,
// importance-weighted pooled accumulate. grid TT/4, block 256 (4 tok x 64 exp).
__global__ void __launch_bounds__(256) pool3_kernel(
    const float* __restrict__ lgp, const float* __restrict__ imp,
    int nW, float* __restrict__ wacc) {
    int tid = threadIdx.x;
    int t = tid >> 6, e = tid & 63;
    int tok = blockIdx.x * 4 + t;
    float l = 0.f;
#pragma unroll
    for (int c = 0; c < 8; c++)
        l += lgp[((size_t)c * TT + tok) * 64 + e];
    float mx = l;
#pragma unroll
    for (int o = 1; o < 16; o <<= 1)
        mx = fmaxf(mx, __shfl_xor_sync(0xffffffffu, mx, o));
    float ev = __expf(l - mx);
    float s = ev;
#pragma unroll
    for (int o = 1; o < 16; o <<= 1)
        s += __shfl_xor_sync(0xffffffffu, s, o);
    if (e < nW * NEXP) {
        int r = e >> 4, n = e & 15, b = tok / SS;
        atomicAdd(&wacc[(r * BB + b) * NEXP + n], imp[tok] * ev / s);
    }
}

__global__ void norm_kernel(float* w, int cnt) {
    int i = threadIdx.x;
    if (i < cnt) {
        float* p = w + i * NEXP;
        float s = 0.f;
        for (int n = 0; n < NEXP; n++) s += p[n];
        float inv = 1.f / (s + 1e-8f);
        for (int n = 0; n < NEXP; n++) p[n] *= inv;
    }
}

// ---------------- pool mixes: out[b, r] = sum_n w[b,n] * P[n, r] ---------------
__global__ void __launch_bounds__(256) mix_kernel(const float* __restrict__ w,
                                                  const float* __restrict__ P,
                                                  float* __restrict__ out) {
    const size_t X = (size_t)DD * RR;
    size_t idx = (size_t)blockIdx.x * 256 + threadIdx.x;
    int b = (int)(idx / X);
    size_t r = idx % X;
    float acc = 0.f;
#pragma unroll
    for (int n = 0; n < NEXP; n++) acc += w[b * NEXP + n] * P[(size_t)n * X + r];
    out[idx] = acc;
}

__global__ void __launch_bounds__(256) mix3_kernel(
    const float* __restrict__ wq, const float* __restrict__ wk,
    const float* __restrict__ wv, const float* __restrict__ P,
    float* __restrict__ eq, float* __restrict__ ek, float* __restrict__ ev) {
    const size_t X = (size_t)RR * DD;
    size_t idx = (size_t)blockIdx.x * 256 + threadIdx.x;
    int b = (int)(idx / X);
    size_t r = idx % X;
    float aq = 0.f, ak = 0.f, av = 0.f;
#pragma unroll
    for (int n = 0; n < NEXP; n++) {
        float p = P[(size_t)n * X + r];
        aq += wq[b * NEXP + n] * p;
        ak += wk[b * NEXP + n] * p;
        av += wv[b * NEXP + n] * p;
    }
    eq[idx] = aq; ek[idx] = ak; ev[idx] = av;
}

// ---------------- tf32 tensor-core GEMM: 128x128 block, BK=16 ------------------
template<bool TRANSB, bool RES>
__global__ void __launch_bounds__(256, 2) tgemm_kernel(
    const float* __restrict__ A, const float* __restrict__ B,
    const float* __restrict__ resp, float* __restrict__ C,
    int M, int N, int K, float alpha,
    long sA, long sB, long sC, long sR) {
    A += (size_t)blockIdx.z * sA;
    B += (size_t)blockIdx.z * sB;
    C += (size_t)blockIdx.z * sC;
    if (RES) resp += (size_t)blockIdx.z * sR;
    const int n0 = blockIdx.x * 128, m0 = blockIdx.y * 128;
    __shared__ float As[128 * 20];
    __shared__ float Bs[2560];
    int tid = threadIdx.x;
    int lane = tid & 31, w = tid >> 5;
    int wm = (w & 1) * 64, wn = (w >> 1) * 32;
    int lq = lane >> 2, lr = lane & 3;

    int rowA = tid >> 2, c4A = (tid & 3) * 4;
    const float* gA = A + (size_t)(m0 + rowA) * K + c4A;
    float* sAp = &As[rowA * 20 + c4A];
    const float* gB;
    float* sBp;
    int gBstep, gBoff2, sBoff2;
    if (!TRANSB) {
        int rB = tid >> 5, cB = (tid & 31) * 4;
        gB = B + (size_t)rB * N + n0 + cB;
        sBp = &Bs[rB * 136 + cB];
        gBstep = 16 * N; gBoff2 = 8 * N; sBoff2 = 8 * 136;
    } else {
        int nB = tid >> 2, c4B = (tid & 3) * 4;
        gB = B + (size_t)(n0 + nB) * K + c4B;
        sBp = &Bs[nB * 20 + c4B];
        gBstep = 16; gBoff2 = 64 * K; sBoff2 = 64 * 20;
    }

    float acc[4][4][4];
#pragma unroll
    for (int mt = 0; mt < 4; mt++)
#pragma unroll
        for (int nt = 0; nt < 4; nt++)
#pragma unroll
            for (int i = 0; i < 4; i++) acc[mt][nt][i] = 0.f;

    float4 pa0 = *(const float4*)gA;
    float4 pa1 = *(const float4*)(gA + (size_t)64 * K);
    float4 pb0 = *(const float4*)gB;
    float4 pb1 = *(const float4*)(gB + gBoff2);

    for (int kt = 0; kt < K; kt += 16) {
        sts4_tf32(sAp, pa0);
        sts4_tf32(sAp + 64 * 20, pa1);
        sts4_tf32(sBp, pb0);
        sts4_tf32(sBp + sBoff2, pb1);
        __syncthreads();
        if (kt + 16 < K) {
            gA += 16;
            pa0 = *(const float4*)gA;
            pa1 = *(const float4*)(gA + (size_t)64 * K);
            gB += gBstep;
            pb0 = *(const float4*)gB;
            pb1 = *(const float4*)(gB + gBoff2);
        }
#pragma unroll
        for (int ks = 0; ks < 16; ks += 8) {
            float af[4][4], bf[4][2];
#pragma unroll
            for (int mt = 0; mt < 4; mt++) {
                int r = wm + mt * 16 + lq;
                af[mt][0] = As[r * 20 + ks + lr];
                af[mt][1] = As[(r + 8) * 20 + ks + lr];
                af[mt][2] = As[r * 20 + ks + lr + 4];
                af[mt][3] = As[(r + 8) * 20 + ks + lr + 4];
            }
#pragma unroll
            for (int nt = 0; nt < 4; nt++) {
                int cc = wn + nt * 8 + lq;
                if (!TRANSB) {
                    bf[nt][0] = Bs[(ks + lr) * 136 + cc];
                    bf[nt][1] = Bs[(ks + 4 + lr) * 136 + cc];
                } else {
                    bf[nt][0] = Bs[cc * 20 + ks + lr];
                    bf[nt][1] = Bs[cc * 20 + ks + 4 + lr];
                }
            }
#pragma unroll
            for (int mt = 0; mt < 4; mt++)
#pragma unroll
                for (int nt = 0; nt < 4; nt++)
                    mma8(acc[mt][nt], af[mt], bf[nt]);
        }
        __syncthreads();
    }
#pragma unroll
    for (int mt = 0; mt < 4; mt++) {
        int r = m0 + wm + mt * 16 + lq;
#pragma unroll
        for (int nt = 0; nt < 4; nt++) {
            int cc = n0 + wn + nt * 8 + 2 * lr;
            float2 v0 = make_float2(alpha * acc[mt][nt][0], alpha * acc[mt][nt][1]);
            float2 v1 = make_float2(alpha * acc[mt][nt][2], alpha * acc[mt][nt][3]);
            size_t o0 = (size_t)r * N + cc;
            size_t o1 = (size_t)(r + 8) * N + cc;
            if (RES) {
                float2 r0 = *(const float2*)(resp + o0);
                float2 r1 = *(const float2*)(resp + o1);
                v0.x += r0.x; v0.y += r0.y;
                v1.x += r1.x; v1.y += r1.y;
            }
            *(float2*)(C + o0) = v0;
            *(float2*)(C + o1) = v1;
        }
    }
}

// ---------------- tf32 tensor-core causal flash attention ----------------------
// BM=128 queries (8 warps x 16), BN=64 keys, dh=64. S and PV via m16n8k8.
// P stays in registers: C-frag -> A-frag via quad shuffles.
__global__ void __launch_bounds__(256, 2) fattn_kernel(
    const float* __restrict__ Q, const float* __restrict__ K,
    const float* __restrict__ V, float* __restrict__ O) {
    int b = blockIdx.z, h = blockIdx.y, q0 = blockIdx.x * 128;
    __shared__ float Ks[64 * 68];
    __shared__ float Vs[64 * 72];
    int tid = threadIdx.x, lane = tid & 31, w = tid >> 5;
    int lq = lane >> 2, lr = lane & 3;
    int wrow = q0 + w * 16;                 // warp's first query row (global)

    // Q fragments, pre-scaled by 1/sqrt(dh)
    float qf[8][4];
    const float* Qb = Q + ((size_t)(b * SS + wrow)) * DD + h * DHD;
#pragma unroll
    for (int ks = 0; ks < 8; ks++) {
        qf[ks][0] = tf32r(0.125f * Qb[lq * DD + ks * 8 + lr]);
        qf[ks][1] = tf32r(0.125f * Qb[(lq + 8) * DD + ks * 8 + lr]);
        qf[ks][2] = tf32r(0.125f * Qb[lq * DD + ks * 8 + lr + 4]);
        qf[ks][3] = tf32r(0.125f * Qb[(lq + 8) * DD + ks * 8 + lr + 4]);
    }
    float of[8][4];
#pragma unroll
    for (int dt = 0; dt < 8; dt++) {
        of[dt][0] = 0.f; of[dt][1] = 0.f; of[dt][2] = 0.f; of[dt][3] = 0.f;
    }
    float m0 = -1e30f, m1 = -1e30f, l0 = 0.f, l1 = 0.f;

    int ntiles = q0 / 64 + 2;
    for (int ti = 0; ti < ntiles; ti++) {
        int j0 = ti * 64;
        __syncthreads();
#pragma unroll
        for (int i = 0; i < 4; i++) {
            int f = tid + 256 * i;
            int r = f >> 4, c4 = (f & 15) * 4;
            size_t goff = ((size_t)(b * SS + j0 + r)) * DD + h * DHD + c4;
            sts4_tf32(&Ks[r * 68 + c4], *(const float4*)(K + goff));
            sts4_tf32(&Vs[r * 72 + c4], *(const float4*)(V + goff));
        }
        __syncthreads();
        if (j0 > wrow + 15) continue;       // tile fully masked for this warp

        // S = Q K^T
        float sc[8][4];
#pragma unroll
        for (int nt = 0; nt < 8; nt++) {
            sc[nt][0] = 0.f; sc[nt][1] = 0.f; sc[nt][2] = 0.f; sc[nt][3] = 0.f;
        }
#pragma unroll
        for (int nt = 0; nt < 8; nt++)
#pragma unroll
            for (int ks = 0; ks < 8; ks++) {
                float bf[2];
                bf[0] = Ks[(nt * 8 + lq) * 68 + ks * 8 + lr];
                bf[1] = Ks[(nt * 8 + lq) * 68 + ks * 8 + lr + 4];
                mma8(sc[nt], qf[ks], bf);
            }
        // causal mask on diagonal-crossing tiles
        if (j0 + 63 > wrow) {
            int r0 = wrow + lq, r1 = r0 + 8;
#pragma unroll
            for (int nt = 0; nt < 8; nt++) {
                int col = j0 + nt * 8 + 2 * lr;
                if (col > r0)     sc[nt][0] = -1e30f;
                if (col + 1 > r0) sc[nt][1] = -1e30f;
                if (col > r1)     sc[nt][2] = -1e30f;
                if (col + 1 > r1) sc[nt][3] = -1e30f;
            }
        }
        // online softmax
        float mx0 = -1e30f, mx1 = -1e30f;
#pragma unroll
        for (int nt = 0; nt < 8; nt++) {
            mx0 = fmaxf(mx0, fmaxf(sc[nt][0], sc[nt][1]));
            mx1 = fmaxf(mx1, fmaxf(sc[nt][2], sc[nt][3]));
        }
        mx0 = fmaxf(mx0, __shfl_xor_sync(0xffffffffu, mx0, 1));
        mx0 = fmaxf(mx0, __shfl_xor_sync(0xffffffffu, mx0, 2));
        mx1 = fmaxf(mx1, __shfl_xor_sync(0xffffffffu, mx1, 1));
        mx1 = fmaxf(mx1, __shfl_xor_sync(0xffffffffu, mx1, 2));
        float mn0 = fmaxf(m0, mx0), mn1 = fmaxf(m1, mx1);
        float f0 = __expf(m0 - mn0), f1 = __expf(m1 - mn1);
        m0 = mn0; m1 = mn1;
        l0 *= f0; l1 *= f1;
#pragma unroll
        for (int dt = 0; dt < 8; dt++) {
            of[dt][0] *= f0; of[dt][1] *= f0;
            of[dt][2] *= f1; of[dt][3] *= f1;
        }
        float rs0 = 0.f, rs1 = 0.f;
#pragma unroll
        for (int nt = 0; nt < 8; nt++) {
            float p0 = tf32r(__expf(sc[nt][0] - m0));
            float p1 = tf32r(__expf(sc[nt][1] - m0));
            float p2 = tf32r(__expf(sc[nt][2] - m1));
            float p3 = tf32r(__expf(sc[nt][3] - m1));
            sc[nt][0] = p0; sc[nt][1] = p1; sc[nt][2] = p2; sc[nt][3] = p3;
            rs0 += p0 + p1; rs1 += p2 + p3;
        }
        rs0 += __shfl_xor_sync(0xffffffffu, rs0, 1);
        rs0 += __shfl_xor_sync(0xffffffffu, rs0, 2);
        rs1 += __shfl_xor_sync(0xffffffffu, rs1, 1);
        rs1 += __shfl_xor_sync(0xffffffffu, rs1, 2);
        l0 += rs0; l1 += rs1;
        // O += P V : permute P C-frag -> A-frag within quads, then mma
        int srcA = (lane & ~3) | (lr >> 1);
        int srcB = srcA | 2;
        bool odd = (lr & 1) != 0;
#pragma unroll
        for (int nt = 0; nt < 8; nt++) {
            float t00 = __shfl_sync(0xffffffffu, sc[nt][0], srcA);
            float t01 = __shfl_sync(0xffffffffu, sc[nt][1], srcA);
            float t02 = __shfl_sync(0xffffffffu, sc[nt][2], srcA);
            float t03 = __shfl_sync(0xffffffffu, sc[nt][3], srcA);
            float u00 = __shfl_sync(0xffffffffu, sc[nt][0], srcB);
            float u01 = __shfl_sync(0xffffffffu, sc[nt][1], srcB);
            float u02 = __shfl_sync(0xffffffffu, sc[nt][2], srcB);
            float u03 = __shfl_sync(0xffffffffu, sc[nt][3], srcB);
            float pa[4];
            pa[0] = odd ? t01 : t00;   // P[lq   ][nt*8+lr  ]
            pa[1] = odd ? t03 : t02;   // P[lq+8 ][nt*8+lr  ]
            pa[2] = odd ? u01 : u00;   // P[lq   ][nt*8+lr+4]
            pa[3] = odd ? u03 : u02;   // P[lq+8 ][nt*8+lr+4]
#pragma unroll
            for (int dt = 0; dt < 8; dt++) {
                float bf[2];
                bf[0] = Vs[(nt * 8 + lr) * 72 + dt * 8 + lq];
                bf[1] = Vs[(nt * 8 + lr + 4) * 72 + dt * 8 + lq];
                mma8(of[dt], pa, bf);
            }
        }
    }
    float inv0 = 1.f / l0, inv1 = 1.f / l1;
    float* Ob0 = O + ((size_t)(b * SS + wrow + lq)) * DD + h * DHD;
    float* Ob1 = Ob0 + (size_t)8 * DD;
#pragma unroll
    for (int dt = 0; dt < 8; dt++) {
        *(float2*)&Ob0[dt * 8 + 2 * lr] = make_float2(of[dt][0] * inv0, of[dt][1] * inv0);
        *(float2*)&Ob1[dt * 8 + 2 * lr] = make_float2(of[dt][2] * inv1, of[dt][3] * inv1);
    }
}

// ---------------- top-8 over 4096 knowledge scores + gather + residual ---------
__global__ void __launch_bounds__(256) topk_kernel(const float* __restrict__ ms,
                                                   const float* __restrict__ x1,
                                                   const float* __restrict__ KV,
                                                   float* __restrict__ out) {
    int token = blockIdx.x;
    __shared__ float sm[NKK];
    __shared__ float rv[256];
    __shared__ int   ri[256];
    __shared__ float tv[TK];
    __shared__ int   ti[TK];
    __shared__ float w8[TK];
    int tid = threadIdx.x;
    const float* row = ms + (size_t)token * NKK;
    for (int i = tid; i < NKK; i += 256) sm[i] = row[i];
    __syncthreads();
    for (int k = 0; k < TK; k++) {
        float bv = -1e30f; int bi = 0x7fffffff;
        for (int i = tid; i < NKK; i += 256) {
            float v = sm[i];
            if (v > bv || (v == bv && i < bi)) { bv = v; bi = i; }
        }
        rv[tid] = bv; ri[tid] = bi;
        __syncthreads();
        for (int s = 128; s; s >>= 1) {
            if (tid < s) {
                float v2 = rv[tid + s]; int i2 = ri[tid + s];
                if (v2 > rv[tid] || (v2 == rv[tid] && i2 < ri[tid])) {
                    rv[tid] = v2; ri[tid] = i2;
                }
            }
            __syncthreads();
        }
        if (tid == 0) { tv[k] = rv[0]; ti[k] = ri[0]; sm[ri[0]] = -1e30f; }
        __syncthreads();
    }
    if (tid == 0) {
        float mx = tv[0];
        float e[TK], s = 0.f;
        for (int k = 0; k < TK; k++) { e[k] = __expf(tv[k] - mx); s += e[k]; }
        float inv = 1.f / s;
        for (int k = 0; k < TK; k++) w8[k] = e[k] * inv;
    }
    __syncthreads();
    for (int d = tid; d < DD; d += 256) {
        float acc = x1[(size_t)token * DD + d];
#pragma unroll
        for (int k = 0; k < TK; k++) acc += w8[k] * KV[(size_t)ti[k] * DD + d];
        out[(size_t)token * DD + d] = acc;
    }
}

// ---------------- driver --------------------------------------------------------
extern "C" void kernel_launch(void* const* d_in, const int* in_sizes, int n_in,
                              void* d_out, int out_size) {
    const float* x   = (const float*)d_in[0];
    const float* imp = (const float*)d_in[1];
    const float* Wc  = (const float*)d_in[2];
    const float* WQ  = (const float*)d_in[3];
    const float* WK  = (const float*)d_in[4];
    const float* WV  = (const float*)d_in[5];
    const float* Wm  = (const float*)d_in[6];
    const float* CN  = (const float*)d_in[7];
    const float* EP  = (const float*)d_in[8];
    const float* kK  = (const float*)d_in[9];
    const float* kV  = (const float*)d_in[10];
    const float* WO  = (const float*)d_in[11];
    const float* g1  = (const float*)d_in[12];
    const float* b1  = (const float*)d_in[13];
    const float* g2  = (const float*)d_in[14];
    const float* b2  = (const float*)d_in[15];
    float* out = (float*)d_out;

    float *nx, *nx2, *w, *wm, *sc, *mc, *h, *qm, *eq, *ek, *ev;
    float *q, *k, *v, *ao, *x1, *msb, *lgp;
    cudaGetSymbolAddress((void**)&nx,  g_nx);
    cudaGetSymbolAddress((void**)&nx2, g_nx2);
    cudaGetSymbolAddress((void**)&w,   g_w);
    cudaGetSymbolAddress((void**)&wm,  g_wm);
    cudaGetSymbolAddress((void**)&sc,  g_sc);
    cudaGetSymbolAddress((void**)&mc,  g_mc);
    cudaGetSymbolAddress((void**)&h,   g_h);
    cudaGetSymbolAddress((void**)&qm,  g_qm);
    cudaGetSymbolAddress((void**)&eq,  g_eq);
    cudaGetSymbolAddress((void**)&ek,  g_ek);
    cudaGetSymbolAddress((void**)&ev,  g_ev);
    cudaGetSymbolAddress((void**)&q,   g_q);
    cudaGetSymbolAddress((void**)&k,   g_k);
    cudaGetSymbolAddress((void**)&v,   g_v);
    cudaGetSymbolAddress((void**)&ao,  g_ao);
    cudaGetSymbolAddress((void**)&x1,  g_x1);
    cudaGetSymbolAddress((void**)&msb, g_ms);
    cudaGetSymbolAddress((void**)&lgp, g_lgp);

    const long SD = (long)SS * DD;
    const long DR = (long)DD * RR;
    const long SR = (long)SS * RR;
    const long RD = (long)RR * DD;
    const long SNK = (long)SS * NKK;

    // ---- attention sub-block ----
    ln_kernel<<<BB * SS, 256>>>(x, g1, b1, nx);
    zero_kernel<<<1, 128>>>(w, 4 * BB * NEXP);
    zero_kernel<<<1, 32>>>(wm, BB * NEXP);
    route3_kernel<<<dim3(TT / 16, 8), 256>>>(nx, Wc, WQ, WK, WV, 64, lgp);
    pool3_kernel<<<TT / 4, 256>>>(lgp, imp, 4, w);
    norm_kernel<<<1, 32>>>(w, 4 * BB);
    mix_kernel<<<(BB * DD * RR) / 256, 256>>>(w, CN, sc);
    mix3_kernel<<<(BB * RR * DD) / 256, 256>>>(w + 1 * BB * NEXP, w + 2 * BB * NEXP,
                                               w + 3 * BB * NEXP, EP, eq, ek, ev);
    tgemm_kernel<false, false><<<dim3(RR / 128, SS / 128, BB), 256>>>(
        nx, sc, nullptr, h, SS, RR, DD, 1.f, SD, DR, SR, 0);
    tgemm_kernel<false, false><<<dim3(DD / 128, SS / 128, BB), 256>>>(
        h, eq, nullptr, q, SS, DD, RR, 1.f, SR, RD, SD, 0);
    tgemm_kernel<false, false><<<dim3(DD / 128, SS / 128, BB), 256>>>(
        h, ek, nullptr, k, SS, DD, RR, 1.f, SR, RD, SD, 0);
    tgemm_kernel<false, false><<<dim3(DD / 128, SS / 128, BB), 256>>>(
        h, ev, nullptr, v, SS, DD, RR, 1.f, SR, RD, SD, 0);
    fattn_kernel<<<dim3(SS / 128, HH, BB), 256>>>(q, k, v, ao);
    tgemm_kernel<true, true><<<dim3(DD / 128, (BB * SS) / 128, 1), 256>>>(
        ao, WO, x, x1, BB * SS, DD, DD, 1.f, 0, 0, 0, 0);

    // ---- memory sub-block ----
    ln_kernel<<<BB * SS, 256>>>(x1, g2, b2, nx2);
    route3_kernel<<<dim3(TT / 16, 8), 256>>>(nx2, Wm, Wm, Wm, Wm, 16, lgp);
    pool3_kernel<<<TT / 4, 256>>>(lgp, imp, 1, wm);
    norm_kernel<<<1, 32>>>(wm, BB);
    mix_kernel<<<(BB * DD * RR) / 256, 256>>>(wm, CN, mc);
    tgemm_kernel<false, false><<<dim3(RR / 128, SS / 128, BB), 256>>>(
        nx2, mc, nullptr, qm, SS, RR, DD, 1.f, SD, DR, SR, 0);
    tgemm_kernel<true, false><<<dim3(NKK / 128, SS / 128, BB), 256>>>(
        qm, kK, nullptr, msb, SS, NKK, RR, 0.0625f, SR, 0, SNK, 0);
    topk_kernel<<<BB * SS, 256>>>(msb, x1, kV, out);
}

// round 7
// speedup vs baseline: 3.2298x; 1.0752x over previous
#include <cuda_runtime.h>
#include <math.h>
#include <stdint.h>

#define BB 2
#define SS 2048
#define DD 1024
#define HH 16
#define DHD 64
#define RR 256
#define NEXP 16
#define NKK 4096
#define TK 8
#define TT (BB*SS)

// ---------------- scratch (device globals; no allocation allowed) -------------
__device__ float g_nx [BB*SS*DD];
__device__ float g_nx2[BB*SS*DD];
__device__ float g_w  [4*BB*NEXP];
__device__ float g_wm [BB*NEXP];
__device__ float g_sc [BB*DD*RR];
__device__ float g_mc [BB*DD*RR];
__device__ float g_h  [BB*SS*RR];
__device__ float g_qm [BB*SS*RR];
__device__ float g_eq [BB*RR*DD];
__device__ float g_ek [BB*RR*DD];
__device__ float g_ev [BB*RR*DD];
__device__ float g_q  [BB*SS*DD];
__device__ float g_k  [BB*SS*DD];
__device__ float g_v  [BB*SS*DD];
__device__ float g_ao [BB*SS*DD];
__device__ float g_x1 [BB*SS*DD];
__device__ float g_ms [(size_t)BB*SS*NKK];
__device__ float g_lgp[(size_t)8*TT*64];

// ---------------- utility ------------------------------------------------------
__global__ void zero2_kernel(float* w, float* wm) {
    int i = threadIdx.x;
    if (i < 128) w[i] = 0.f;
    else if (i < 160) wm[i - 128] = 0.f;
}

__device__ __forceinline__ float tf32r(float x) {
    uint32_t u;
    asm("cvt.rna.tf32.f32 %0, %1;" : "=r"(u) : "f"(x));
    return __uint_as_float(u);
}

__device__ __forceinline__ void sts4_tf32(float* p, float4 v) {
    float4 o;
    o.x = tf32r(v.x); o.y = tf32r(v.y); o.z = tf32r(v.z); o.w = tf32r(v.w);
    *(float4*)p = o;
}

__device__ __forceinline__ void mma8(float* c, const float* a, const float* b) {
    uint32_t A0 = __float_as_uint(a[0]), A1 = __float_as_uint(a[1]);
    uint32_t A2 = __float_as_uint(a[2]), A3 = __float_as_uint(a[3]);
    uint32_t B0 = __float_as_uint(b[0]), B1 = __float_as_uint(b[1]);
    asm volatile(
        "mma.sync.aligned.m16n8k8.row.col.f32.tf32.tf32.f32 "
        "{%0,%1,%2,%3}, {%4,%5,%6,%7}, {%8,%9}, {%0,%1,%2,%3};\n"
        : "+f"(c[0]), "+f"(c[1]), "+f"(c[2]), "+f"(c[3])
        : "r"(A0), "r"(A1), "r"(A2), "r"(A3), "r"(B0), "r"(B1));
}

// ---------------- LayerNorm: one block per row, 256 threads --------------------
__global__ void __launch_bounds__(256) ln_kernel(const float* __restrict__ x,
                                                 const float* __restrict__ g,
                                                 const float* __restrict__ b,
                                                 float* __restrict__ out) {
    int row = blockIdx.x;
    const float4* xr = (const float4*)(x + (size_t)row * DD);
    float4 t = xr[threadIdx.x];
    float s  = t.x + t.y + t.z + t.w;
    float sq = t.x*t.x + t.y*t.y + t.z*t.z + t.w*t.w;
    __shared__ float rs[8], rq[8];
    for (int o = 16; o; o >>= 1) {
        s  += __shfl_down_sync(0xffffffffu, s,  o);
        sq += __shfl_down_sync(0xffffffffu, sq, o);
    }
    int wid = threadIdx.x >> 5, lane = threadIdx.x & 31;
    if (lane == 0) { rs[wid] = s; rq[wid] = sq; }
    __syncthreads();
    if (threadIdx.x == 0) {
        float a = 0.f, c = 0.f;
        for (int i = 0; i < 8; i++) { a += rs[i]; c += rq[i]; }
        rs[0] = a; rq[0] = c;
    }
    __syncthreads();
    float mean = rs[0] * (1.f / DD);
    float var  = rq[0] * (1.f / DD) - mean * mean;
    float rstd = rsqrtf(var + 1e-5f);
    float4 gg = ((const float4*)g)[threadIdx.x];
    float4 bb = ((const float4*)b)[threadIdx.x];
    float4 o4;
    o4.x = (t.x - mean) * rstd * gg.x + bb.x;
    o4.y = (t.y - mean) * rstd * gg.y + bb.y;
    o4.z = (t.z - mean) * rstd * gg.z + bb.z;
    o4.w = (t.w - mean) * rstd * gg.w + bb.w;
    ((float4*)(out + (size_t)row * DD))[threadIdx.x] = o4;
}

// ---------------- routing v4: 4 tok x 4 exp register blocking ------------------
// grid (TT/16, 8). Thread (dq,tg,eg): tokens tg*4..+3, experts eg+16i, 32-wide
// D quarter dq. Partials reduced in smem (reusing ws), lgp layout unchanged.
__global__ void __launch_bounds__(256) route4_kernel(
    const float* __restrict__ nx,
    const float* __restrict__ W0, const float* __restrict__ W1,
    const float* __restrict__ W2, const float* __restrict__ W3,
    int nE, float* __restrict__ lgp) {
    __shared__ float xs[16 * 132];
    __shared__ float ws[64 * 132];   // reused as partials [4][16][68] after compute
    int tid = threadIdx.x;
    int tok0 = blockIdx.x * 16;
    int c = blockIdx.y;
    int dq = tid >> 6, tg = (tid >> 4) & 3, eg = tid & 15;
    const float* Ws[4] = {W0, W1, W2, W3};
#pragma unroll
    for (int i = 0; i < 2; i++) {
        int f = tid + 256 * i;
        int tt = f >> 5, d4 = f & 31;
        *(float4*)&xs[tt * 132 + d4 * 4] =
            *(const float4*)(nx + (size_t)(tok0 + tt) * DD + c * 128 + d4 * 4);
    }
#pragma unroll
    for (int i = 0; i < 8; i++) {
        int f = tid + 256 * i;
        if (f < nE * 32) {
            int e = f >> 5, d4 = f & 31;
            const float* src = Ws[e >> 4] + (size_t)(e & 15) * DD + c * 128 + d4 * 4;
            *(float4*)&ws[e * 132 + d4 * 4] = *(const float4*)src;
        }
    }
    __syncthreads();
    bool em[4];
#pragma unroll
    for (int i = 0; i < 4; i++) em[i] = (eg + i * 16) < nE;
    float a[4][4];
#pragma unroll
    for (int j = 0; j < 4; j++)
#pragma unroll
        for (int i = 0; i < 4; i++) a[j][i] = 0.f;
#pragma unroll
    for (int d4 = dq * 8; d4 < dq * 8 + 8; d4++) {
        float4 xv[4], wv[4];
#pragma unroll
        for (int j = 0; j < 4; j++)
            xv[j] = *(float4*)&xs[(tg * 4 + j) * 132 + d4 * 4];
#pragma unroll
        for (int i = 0; i < 4; i++)
            wv[i] = em[i] ? *(float4*)&ws[(eg + i * 16) * 132 + d4 * 4]
                          : make_float4(0.f, 0.f, 0.f, 0.f);
#pragma unroll
        for (int j = 0; j < 4; j++)
#pragma unroll
            for (int i = 0; i < 4; i++)
                a[j][i] += xv[j].x * wv[i].x + xv[j].y * wv[i].y +
                           xv[j].z * wv[i].z + xv[j].w * wv[i].w;
    }
    __syncthreads();
    float* part = ws;     // [dq][t(16)][68]
#pragma unroll
    for (int j = 0; j < 4; j++)
#pragma unroll
        for (int i = 0; i < 4; i++)
            part[dq * 1088 + (tg * 4 + j) * 68 + eg + i * 16] = a[j][i];
    __syncthreads();
    {
        int t = tid >> 4, e0 = (tid * 4) & 63;
        float4 s = make_float4(0.f, 0.f, 0.f, 0.f);
#pragma unroll
        for (int d = 0; d < 4; d++) {
            float4 p = *(float4*)&part[d * 1088 + t * 68 + e0];
            s.x += p.x; s.y += p.y; s.z += p.z; s.w += p.w;
        }
        *(float4*)&lgp[((size_t)c * TT + tok0 + t) * 64 + e0] = s;
    }
}

// pool partials: sum 8 chunks, softmax within 16-expert router segments,
// importance-weighted pooled accumulate. grid TT/4, block 256.
__global__ void __launch_bounds__(256) pool3_kernel(
    const float* __restrict__ lgp, const float* __restrict__ imp,
    int nW, float* __restrict__ wacc) {
    int tid = threadIdx.x;
    int t = tid >> 6, e = tid & 63;
    int tok = blockIdx.x * 4 + t;
    float l = 0.f;
#pragma unroll
    for (int c = 0; c < 8; c++)
        l += lgp[((size_t)c * TT + tok) * 64 + e];
    float mx = l;
#pragma unroll
    for (int o = 1; o < 16; o <<= 1)
        mx = fmaxf(mx, __shfl_xor_sync(0xffffffffu, mx, o));
    float ev = __expf(l - mx);
    float s = ev;
#pragma unroll
    for (int o = 1; o < 16; o <<= 1)
        s += __shfl_xor_sync(0xffffffffu, s, o);
    if (e < nW * NEXP) {
        int r = e >> 4, n = e & 15, b = tok / SS;
        atomicAdd(&wacc[(r * BB + b) * NEXP + n], imp[tok] * ev / s);
    }
}

__global__ void norm_kernel(float* w, int cnt) {
    int i = threadIdx.x;
    if (i < cnt) {
        float* p = w + i * NEXP;
        float s = 0.f;
        for (int n = 0; n < NEXP; n++) s += p[n];
        float inv = 1.f / (s + 1e-8f);
        for (int n = 0; n < NEXP; n++) p[n] *= inv;
    }
}

// ---------------- pool mixes (fused attention-block version + plain) -----------
__global__ void __launch_bounds__(256) mix_kernel(const float* __restrict__ w,
                                                  const float* __restrict__ P,
                                                  float* __restrict__ out) {
    const size_t X = (size_t)DD * RR;
    size_t idx = (size_t)blockIdx.x * 256 + threadIdx.x;
    int b = (int)(idx / X);
    size_t r = idx % X;
    float acc = 0.f;
#pragma unroll
    for (int n = 0; n < NEXP; n++) acc += w[b * NEXP + n] * P[(size_t)n * X + r];
    out[idx] = acc;
}

// first 2048 blocks: sc = cw . CN ; next 2048: eq/ek/ev = wq/wk/wv . EP
__global__ void __launch_bounds__(256) mixfused_kernel(
    const float* __restrict__ w, const float* __restrict__ CN,
    const float* __restrict__ EP, float* __restrict__ sc,
    float* __restrict__ eq, float* __restrict__ ek, float* __restrict__ ev) {
    const size_t X = (size_t)DD * RR;
    if (blockIdx.x < 2048) {
        size_t idx = (size_t)blockIdx.x * 256 + threadIdx.x;
        int b = (int)(idx / X);
        size_t r = idx % X;
        float acc = 0.f;
#pragma unroll
        for (int n = 0; n < NEXP; n++) acc += w[b * NEXP + n] * CN[(size_t)n * X + r];
        sc[idx] = acc;
    } else {
        size_t idx = (size_t)(blockIdx.x - 2048) * 256 + threadIdx.x;
        int b = (int)(idx / X);
        size_t r = idx % X;
        const float* wq = w + 32;
        const float* wk = w + 64;
        const float* wv = w + 96;
        float aq = 0.f, ak = 0.f, av = 0.f;
#pragma unroll
        for (int n = 0; n < NEXP; n++) {
            float p = EP[(size_t)n * X + r];
            aq += wq[b * NEXP + n] * p;
            ak += wk[b * NEXP + n] * p;
            av += wv[b * NEXP + n] * p;
        }
        eq[idx] = aq; ek[idx] = ak; ev[idx] = av;
    }
}

// ---------------- tf32 tensor-core GEMM body: 128x128 block, BK=16 -------------
template<bool TRANSB, bool RES>
__device__ __forceinline__ void tgemm_body(
    const float* __restrict__ A, const float* __restrict__ B,
    const float* __restrict__ resp, float* __restrict__ C,
    int N, int K, float alpha) {
    const int n0 = blockIdx.x * 128, m0 = blockIdx.y * 128;
    __shared__ float As[128 * 20];
    __shared__ float Bs[2560];
    int tid = threadIdx.x;
    int lane = tid & 31, w = tid >> 5;
    int wm = (w & 1) * 64, wn = (w >> 1) * 32;
    int lq = lane >> 2, lr = lane & 3;

    int rowA = tid >> 2, c4A = (tid & 3) * 4;
    const float* gA = A + (size_t)(m0 + rowA) * K + c4A;
    float* sAp = &As[rowA * 20 + c4A];
    const float* gB;
    float* sBp;
    int gBstep, gBoff2, sBoff2;
    if (!TRANSB) {
        int rB = tid >> 5, cB = (tid & 31) * 4;
        gB = B + (size_t)rB * N + n0 + cB;
        sBp = &Bs[rB * 136 + cB];
        gBstep = 16 * N; gBoff2 = 8 * N; sBoff2 = 8 * 136;
    } else {
        int nB = tid >> 2, c4B = (tid & 3) * 4;
        gB = B + (size_t)(n0 + nB) * K + c4B;
        sBp = &Bs[nB * 20 + c4B];
        gBstep = 16; gBoff2 = 64 * K; sBoff2 = 64 * 20;
    }

    float acc[4][4][4];
#pragma unroll
    for (int mt = 0; mt < 4; mt++)
#pragma unroll
        for (int nt = 0; nt < 4; nt++)
#pragma unroll
            for (int i = 0; i < 4; i++) acc[mt][nt][i] = 0.f;

    float4 pa0 = *(const float4*)gA;
    float4 pa1 = *(const float4*)(gA + (size_t)64 * K);
    float4 pb0 = *(const float4*)gB;
    float4 pb1 = *(const float4*)(gB + gBoff2);

    for (int kt = 0; kt < K; kt += 16) {
        sts4_tf32(sAp, pa0);
        sts4_tf32(sAp + 64 * 20, pa1);
        sts4_tf32(sBp, pb0);
        sts4_tf32(sBp + sBoff2, pb1);
        __syncthreads();
        if (kt + 16 < K) {
            gA += 16;
            pa0 = *(const float4*)gA;
            pa1 = *(const float4*)(gA + (size_t)64 * K);
            gB += gBstep;
            pb0 = *(const float4*)gB;
            pb1 = *(const float4*)(gB + gBoff2);
        }
#pragma unroll
        for (int ks = 0; ks < 16; ks += 8) {
            float af[4][4], bf[4][2];
#pragma unroll
            for (int mt = 0; mt < 4; mt++) {
                int r = wm + mt * 16 + lq;
                af[mt][0] = As[r * 20 + ks + lr];
                af[mt][1] = As[(r + 8) * 20 + ks + lr];
                af[mt][2] = As[r * 20 + ks + lr + 4];
                af[mt][3] = As[(r + 8) * 20 + ks + lr + 4];
            }
#pragma unroll
            for (int nt = 0; nt < 4; nt++) {
                int cc = wn + nt * 8 + lq;
                if (!TRANSB) {
                    bf[nt][0] = Bs[(ks + lr) * 136 + cc];
                    bf[nt][1] = Bs[(ks + 4 + lr) * 136 + cc];
                } else {
                    bf[nt][0] = Bs[cc * 20 + ks + lr];
                    bf[nt][1] = Bs[cc * 20 + ks + 4 + lr];
                }
            }
#pragma unroll
            for (int mt = 0; mt < 4; mt++)
#pragma unroll
                for (int nt = 0; nt < 4; nt++)
                    mma8(acc[mt][nt], af[mt], bf[nt]);
        }
        __syncthreads();
    }
#pragma unroll
    for (int mt = 0; mt < 4; mt++) {
        int r = m0 + wm + mt * 16 + lq;
#pragma unroll
        for (int nt = 0; nt < 4; nt++) {
            int cc = n0 + wn + nt * 8 + 2 * lr;
            float2 v0 = make_float2(alpha * acc[mt][nt][0], alpha * acc[mt][nt][1]);
            float2 v1 = make_float2(alpha * acc[mt][nt][2], alpha * acc[mt][nt][3]);
            size_t o0 = (size_t)r * N + cc;
            size_t o1 = (size_t)(r + 8) * N + cc;
            if (RES) {
                float2 r0 = *(const float2*)(resp + o0);
                float2 r1 = *(const float2*)(resp + o1);
                v0.x += r0.x; v0.y += r0.y;
                v1.x += r1.x; v1.y += r1.y;
            }
            *(float2*)(C + o0) = v0;
            *(float2*)(C + o1) = v1;
        }
    }
}

template<bool TRANSB, bool RES>
__global__ void __launch_bounds__(256, 2) tgemm_kernel(
    const float* __restrict__ A, const float* __restrict__ B,
    const float* __restrict__ resp, float* __restrict__ C,
    int N, int K, float alpha, long sA, long sB, long sC, long sR) {
    A += (size_t)blockIdx.z * sA;
    B += (size_t)blockIdx.z * sB;
    C += (size_t)blockIdx.z * sC;
    if (RES) resp += (size_t)blockIdx.z * sR;
    tgemm_body<TRANSB, RES>(A, B, resp, C, N, K, alpha);
}

// merged Q/K/V projection: grid.z = 6 (which = z>>1, b = z&1)
__global__ void __launch_bounds__(256, 2) qkv_kernel(
    const float* __restrict__ h,
    const float* __restrict__ eq, const float* __restrict__ ek,
    const float* __restrict__ ev,
    float* __restrict__ q, float* __restrict__ k, float* __restrict__ v) {
    int z = blockIdx.z;
    int b = z & 1, which = z >> 1;
    const float* B = (which == 0 ? eq : which == 1 ? ek : ev) + (size_t)b * RR * DD;
    float* C = (which == 0 ? q : which == 1 ? k : v) + (size_t)b * SS * DD;
    const float* A = h + (size_t)b * SS * RR;
    tgemm_body<false, false>(A, B, nullptr, C, DD, RR, 1.f);
}

// ---------------- tf32 tensor-core causal flash attention ----------------------
// BM=128 queries (8 warps x 16), BN=64 keys, dh=64. Blocks reversed so the
// longest (high-q0) tiles are scheduled first for better tail packing.
__global__ void __launch_bounds__(256, 2) fattn_kernel(
    const float* __restrict__ Q, const float* __restrict__ K,
    const float* __restrict__ V, float* __restrict__ O) {
    int b = blockIdx.z, h = blockIdx.y;
    int q0 = (gridDim.x - 1 - blockIdx.x) * 128;
    __shared__ float Ks[64 * 68];
    __shared__ float Vs[64 * 72];
    int tid = threadIdx.x, lane = tid & 31, w = tid >> 5;
    int lq = lane >> 2, lr = lane & 3;
    int wrow = q0 + w * 16;

    float qf[8][4];
    const float* Qb = Q + ((size_t)(b * SS + wrow)) * DD + h * DHD;
#pragma unroll
    for (int ks = 0; ks < 8; ks++) {
        qf[ks][0] = tf32r(0.125f * Qb[lq * DD + ks * 8 + lr]);
        qf[ks][1] = tf32r(0.125f * Qb[(lq + 8) * DD + ks * 8 + lr]);
        qf[ks][2] = tf32r(0.125f * Qb[lq * DD + ks * 8 + lr + 4]);
        qf[ks][3] = tf32r(0.125f * Qb[(lq + 8) * DD + ks * 8 + lr + 4]);
    }
    float of[8][4];
#pragma unroll
    for (int dt = 0; dt < 8; dt++) {
        of[dt][0] = 0.f; of[dt][1] = 0.f; of[dt][2] = 0.f; of[dt][3] = 0.f;
    }
    float m0 = -1e30f, m1 = -1e30f, l0 = 0.f, l1 = 0.f;

    int ntiles = q0 / 64 + 2;
    for (int ti = 0; ti < ntiles; ti++) {
        int j0 = ti * 64;
        __syncthreads();
#pragma unroll
        for (int i = 0; i < 4; i++) {
            int f = tid + 256 * i;
            int r = f >> 4, c4 = (f & 15) * 4;
            size_t goff = ((size_t)(b * SS + j0 + r)) * DD + h * DHD + c4;
            sts4_tf32(&Ks[r * 68 + c4], *(const float4*)(K + goff));
            sts4_tf32(&Vs[r * 72 + c4], *(const float4*)(V + goff));
        }
        __syncthreads();
        if (j0 > wrow + 15) continue;

        float sc[8][4];
#pragma unroll
        for (int nt = 0; nt < 8; nt++) {
            sc[nt][0] = 0.f; sc[nt][1] = 0.f; sc[nt][2] = 0.f; sc[nt][3] = 0.f;
        }
#pragma unroll
        for (int nt = 0; nt < 8; nt++)
#pragma unroll
            for (int ks = 0; ks < 8; ks++) {
                float bf[2];
                bf[0] = Ks[(nt * 8 + lq) * 68 + ks * 8 + lr];
                bf[1] = Ks[(nt * 8 + lq) * 68 + ks * 8 + lr + 4];
                mma8(sc[nt], qf[ks], bf);
            }
        if (j0 + 63 > wrow) {
            int r0 = wrow + lq, r1 = r0 + 8;
#pragma unroll
            for (int nt = 0; nt < 8; nt++) {
                int col = j0 + nt * 8 + 2 * lr;
                if (col > r0)     sc[nt][0] = -1e30f;
                if (col + 1 > r0) sc[nt][1] = -1e30f;
                if (col > r1)     sc[nt][2] = -1e30f;
                if (col + 1 > r1) sc[nt][3] = -1e30f;
            }
        }
        float mx0 = -1e30f, mx1 = -1e30f;
#pragma unroll
        for (int nt = 0; nt < 8; nt++) {
            mx0 = fmaxf(mx0, fmaxf(sc[nt][0], sc[nt][1]));
            mx1 = fmaxf(mx1, fmaxf(sc[nt][2], sc[nt][3]));
        }
        mx0 = fmaxf(mx0, __shfl_xor_sync(0xffffffffu, mx0, 1));
        mx0 = fmaxf(mx0, __shfl_xor_sync(0xffffffffu, mx0, 2));
        mx1 = fmaxf(mx1, __shfl_xor_sync(0xffffffffu, mx1, 1));
        mx1 = fmaxf(mx1, __shfl_xor_sync(0xffffffffu, mx1, 2));
        float mn0 = fmaxf(m0, mx0), mn1 = fmaxf(m1, mx1);
        float f0 = __expf(m0 - mn0), f1 = __expf(m1 - mn1);
        m0 = mn0; m1 = mn1;
        l0 *= f0; l1 *= f1;
#pragma unroll
        for (int dt = 0; dt < 8; dt++) {
            of[dt][0] *= f0; of[dt][1] *= f0;
            of[dt][2] *= f1; of[dt][3] *= f1;
        }
        float rs0 = 0.f, rs1 = 0.f;
#pragma unroll
        for (int nt = 0; nt < 8; nt++) {
            float p0 = tf32r(__expf(sc[nt][0] - m0));
            float p1 = tf32r(__expf(sc[nt][1] - m0));
            float p2 = tf32r(__expf(sc[nt][2] - m1));
            float p3 = tf32r(__expf(sc[nt][3] - m1));
            sc[nt][0] = p0; sc[nt][1] = p1; sc[nt][2] = p2; sc[nt][3] = p3;
            rs0 += p0 + p1; rs1 += p2 + p3;
        }
        rs0 += __shfl_xor_sync(0xffffffffu, rs0, 1);
        rs0 += __shfl_xor_sync(0xffffffffu, rs0, 2);
        rs1 += __shfl_xor_sync(0xffffffffu, rs1, 1);
        rs1 += __shfl_xor_sync(0xffffffffu, rs1, 2);
        l0 += rs0; l1 += rs1;
        int srcA = (lane & ~3) | (lr >> 1);
        int srcB = srcA | 2;
        bool odd = (lr & 1) != 0;
#pragma unroll
        for (int nt = 0; nt < 8; nt++) {
            float t00 = __shfl_sync(0xffffffffu, sc[nt][0], srcA);
            float t01 = __shfl_sync(0xffffffffu, sc[nt][1], srcA);
            float t02 = __shfl_sync(0xffffffffu, sc[nt][2], srcA);
            float t03 = __shfl_sync(0xffffffffu, sc[nt][3], srcA);
            float u00 = __shfl_sync(0xffffffffu, sc[nt][0], srcB);
            float u01 = __shfl_sync(0xffffffffu, sc[nt][1], srcB);
            float u02 = __shfl_sync(0xffffffffu, sc[nt][2], srcB);
            float u03 = __shfl_sync(0xffffffffu, sc[nt][3], srcB);
            float pa[4];
            pa[0] = odd ? t01 : t00;
            pa[1] = odd ? t03 : t02;
            pa[2] = odd ? u01 : u00;
            pa[3] = odd ? u03 : u02;
#pragma unroll
            for (int dt = 0; dt < 8; dt++) {
                float bf[2];
                bf[0] = Vs[(nt * 8 + lr) * 72 + dt * 8 + lq];
                bf[1] = Vs[(nt * 8 + lr + 4) * 72 + dt * 8 + lq];
                mma8(of[dt], pa, bf);
            }
        }
    }
    float inv0 = 1.f / l0, inv1 = 1.f / l1;
    float* Ob0 = O + ((size_t)(b * SS + wrow + lq)) * DD + h * DHD;
    float* Ob1 = Ob0 + (size_t)8 * DD;
#pragma unroll
    for (int dt = 0; dt < 8; dt++) {
        *(float2*)&Ob0[dt * 8 + 2 * lr] = make_float2(of[dt][0] * inv0, of[dt][1] * inv0);
        *(float2*)&Ob1[dt * 8 + 2 * lr] = make_float2(of[dt][2] * inv1, of[dt][3] * inv1);
    }
}

// ---------------- top-8 v2: register candidates + warp argmax rounds -----------
__global__ void __launch_bounds__(256) topk2_kernel(const float* __restrict__ ms,
                                                    const float* __restrict__ x1,
                                                    const float* __restrict__ KV,
                                                    float* __restrict__ out) {
    int token = blockIdx.x;
    int tid = threadIdx.x, w = tid >> 5, lane = tid & 31;
    const float* row = ms + (size_t)token * NKK;
    // lane holds 16 values: r[i*4+j] <-> global idx w*512 + i*128 + lane*4 + j
    float r[16];
#pragma unroll
    for (int i = 0; i < 4; i++) {
        float4 t4 = *(const float4*)(row + w * 512 + i * 128 + lane * 4);
        r[i * 4 + 0] = t4.x; r[i * 4 + 1] = t4.y;
        r[i * 4 + 2] = t4.z; r[i * 4 + 3] = t4.w;
    }
    __shared__ float cv_s[64];
    __shared__ int   ci_s[64];
    __shared__ float tv[TK];
    __shared__ int   tix[TK];
    __shared__ float w8[TK];
    uint32_t taken = 0;
    for (int k = 0; k < TK; k++) {
        float bv = -1e30f; int bi = 0;
#pragma unroll
        for (int i = 0; i < 16; i++) {
            if (!((taken >> i) & 1u) && r[i] > bv) { bv = r[i]; bi = i; }
        }
        int mygi = w * 512 + (bi >> 2) * 128 + lane * 4 + (bi & 3);
        float rv = bv; int gi = mygi;
#pragma unroll
        for (int o = 16; o; o >>= 1) {
            float ov = __shfl_xor_sync(0xffffffffu, rv, o);
            int   oi = __shfl_xor_sync(0xffffffffu, gi, o);
            if (ov > rv || (ov == rv && oi < gi)) { rv = ov; gi = oi; }
        }
        if (gi == mygi) taken |= 1u << bi;
        if (lane == 0) { cv_s[w * 8 + k] = rv; ci_s[w * 8 + k] = gi; }
    }
    __syncthreads();
    if (w == 0) {
        float c0 = cv_s[lane], c1 = cv_s[lane + 32];
        int i0 = ci_s[lane], i1 = ci_s[lane + 32];
        uint32_t tk = 0;
        for (int k = 0; k < TK; k++) {
            float bv = -1e30f; int gi = 0x7fffffff; int sel = -1;
            if (!(tk & 1u)) { bv = c0; gi = i0; sel = 0; }
            if (!(tk & 2u) && (c1 > bv || (c1 == bv && i1 < gi))) {
                bv = c1; gi = i1; sel = 1;
            }
            float rv = bv; int g = gi;
#pragma unroll
            for (int o = 16; o; o >>= 1) {
                float ov = __shfl_xor_sync(0xffffffffu, rv, o);
                int   oi = __shfl_xor_sync(0xffffffffu, g, o);
                if (ov > rv || (ov == rv && oi < g)) { rv = ov; g = oi; }
            }
            if (sel >= 0 && g == gi) tk |= (sel ? 2u : 1u);
            if (lane == 0) { tv[k] = rv; tix[k] = g; }
        }
        if (lane == 0) {
            float mx = tv[0];
            float e[TK], s = 0.f;
            for (int k = 0; k < TK; k++) { e[k] = __expf(tv[k] - mx); s += e[k]; }
            float inv = 1.f / s;
            for (int k = 0; k < TK; k++) w8[k] = e[k] * inv;
        }
    }
    __syncthreads();
    {
        float4 acc = *(const float4*)(x1 + (size_t)token * DD + tid * 4);
#pragma unroll
        for (int k = 0; k < TK; k++) {
            float4 kv = *(const float4*)(KV + (size_t)tix[k] * DD + tid * 4);
            float wk = w8[k];
            acc.x += wk * kv.x; acc.y += wk * kv.y;
            acc.z += wk * kv.z; acc.w += wk * kv.w;
        }
        *(float4*)(out + (size_t)token * DD + tid * 4) = acc;
    }
}

// ---------------- driver --------------------------------------------------------
extern "C" void kernel_launch(void* const* d_in, const int* in_sizes, int n_in,
                              void* d_out, int out_size) {
    const float* x   = (const float*)d_in[0];
    const float* imp = (const float*)d_in[1];
    const float* Wc  = (const float*)d_in[2];
    const float* WQ  = (const float*)d_in[3];
    const float* WK  = (const float*)d_in[4];
    const float* WV  = (const float*)d_in[5];
    const float* Wm  = (const float*)d_in[6];
    const float* CN  = (const float*)d_in[7];
    const float* EP  = (const float*)d_in[8];
    const float* kK  = (const float*)d_in[9];
    const float* kV  = (const float*)d_in[10];
    const float* WO  = (const float*)d_in[11];
    const float* g1  = (const float*)d_in[12];
    const float* b1  = (const float*)d_in[13];
    const float* g2  = (const float*)d_in[14];
    const float* b2  = (const float*)d_in[15];
    float* out = (float*)d_out;

    float *nx, *nx2, *w, *wm, *sc, *mc, *h, *qm, *eq, *ek, *ev;
    float *q, *k, *v, *ao, *x1, *msb, *lgp;
    cudaGetSymbolAddress((void**)&nx,  g_nx);
    cudaGetSymbolAddress((void**)&nx2, g_nx2);
    cudaGetSymbolAddress((void**)&w,   g_w);
    cudaGetSymbolAddress((void**)&wm,  g_wm);
    cudaGetSymbolAddress((void**)&sc,  g_sc);
    cudaGetSymbolAddress((void**)&mc,  g_mc);
    cudaGetSymbolAddress((void**)&h,   g_h);
    cudaGetSymbolAddress((void**)&qm,  g_qm);
    cudaGetSymbolAddress((void**)&eq,  g_eq);
    cudaGetSymbolAddress((void**)&ek,  g_ek);
    cudaGetSymbolAddress((void**)&ev,  g_ev);
    cudaGetSymbolAddress((void**)&q,   g_q);
    cudaGetSymbolAddress((void**)&k,   g_k);
    cudaGetSymbolAddress((void**)&v,   g_v);
    cudaGetSymbolAddress((void**)&ao,  g_ao);
    cudaGetSymbolAddress((void**)&x1,  g_x1);
    cudaGetSymbolAddress((void**)&msb, g_ms);
    cudaGetSymbolAddress((void**)&lgp, g_lgp);

    const long SD = (long)SS * DD;
    const long DR = (long)DD * RR;
    const long SR = (long)SS * RR;
    const long SNK = (long)SS * NKK;

    // ---- attention sub-block ----
    ln_kernel<<<BB * SS, 256>>>(x, g1, b1, nx);
    zero2_kernel<<<1, 160>>>(w, wm);
    route4_kernel<<<dim3(TT / 16, 8), 256>>>(nx, Wc, WQ, WK, WV, 64, lgp);
    pool3_kernel<<<TT / 4, 256>>>(lgp, imp, 4, w);
    norm_kernel<<<1, 32>>>(w, 4 * BB);
    mixfused_kernel<<<4096, 256>>>(w, CN, EP, sc, eq, ek, ev);
    tgemm_kernel<false, false><<<dim3(RR / 128, SS / 128, BB), 256>>>(
        nx, sc, nullptr, h, RR, DD, 1.f, SD, DR, SR, 0);
    qkv_kernel<<<dim3(DD / 128, SS / 128, 6), 256>>>(h, eq, ek, ev, q, k, v);
    fattn_kernel<<<dim3(SS / 128, HH, BB), 256>>>(q, k, v, ao);
    tgemm_kernel<true, true><<<dim3(DD / 128, (BB * SS) / 128, 1), 256>>>(
        ao, WO, x, x1, DD, DD, 1.f, 0, 0, 0, 0);

    // ---- memory sub-block ----
    ln_kernel<<<BB * SS, 256>>>(x1, g2, b2, nx2);
    route4_kernel<<<dim3(TT / 16, 8), 256>>>(nx2, Wm, Wm, Wm, Wm, 16, lgp);
    pool3_kernel<<<TT / 4, 256>>>(lgp, imp, 1, wm);
    norm_kernel<<<1, 32>>>(wm, BB);
    mix_kernel<<<(BB * DD * RR) / 256, 256>>>(wm, CN, mc);
    tgemm_kernel<false, false><<<dim3(RR / 128, SS / 128, BB), 256>>>(
        nx2, mc, nullptr, qm, RR, DD, 1.f, SD, DR, SR, 0);
    tgemm_kernel<true, false><<<dim3(NKK / 128, SS / 128, BB), 256>>>(
        qm, kK, nullptr, msb, NKK, RR, 0.0625f, SR, 0, SNK, 0);
    topk2_kernel<<<BB * SS, 256>>>(msb, x1, kV, out);
}

// round 8
// speedup vs baseline: 3.4111x; 1.0561x over previous
#include <cuda_runtime.h>
#include <cuda_bf16.h>
#include <math.h>
#include <stdint.h>

#define BB 2
#define SS 2048
#define DD 1024
#define HH 16
#define DHD 64
#define RR 256
#define NEXP 16
#define NKK 4096
#define TK 8
#define TT (BB*SS)

// ---------------- scratch (device globals; no allocation allowed) -------------
__device__ float g_nx [BB*SS*DD];
__device__ float g_nx2[BB*SS*DD];
__device__ float g_w  [4*BB*NEXP];
__device__ float g_wm [BB*NEXP];
__device__ float g_sc [BB*DD*RR];
__device__ float g_mc [BB*DD*RR];
__device__ float g_h  [BB*SS*RR];
__device__ float g_qm [BB*SS*RR];
__device__ float g_eq [BB*RR*DD];
__device__ float g_ek [BB*RR*DD];
__device__ float g_ev [BB*RR*DD];
__device__ float g_q  [BB*SS*DD];
__device__ float g_k  [BB*SS*DD];
__device__ float g_v  [BB*SS*DD];
__device__ float g_ao [BB*SS*DD];
__device__ float g_x1 [BB*SS*DD];
__device__ float g_ms [(size_t)BB*SS*NKK];   // used as bf16 (half capacity)
__device__ float g_lgp[(size_t)4*TT*64];

// ---------------- utility ------------------------------------------------------
// zero h, qm (1M floats each) + w/wm accumulators. grid 1024 x 256 (float4).
__global__ void __launch_bounds__(256) zeroall_kernel(float4* h4, float4* q4,
                                                      float* w, float* wm) {
    int i = blockIdx.x * 256 + threadIdx.x;
    float4 z = make_float4(0.f, 0.f, 0.f, 0.f);
    h4[i] = z; q4[i] = z;
    if (blockIdx.x == 0) {
        if (threadIdx.x < 128) w[threadIdx.x] = 0.f;
        else if (threadIdx.x < 160) wm[threadIdx.x - 128] = 0.f;
    }
}

__device__ __forceinline__ float tf32r(float x) {
    uint32_t u;
    asm("cvt.rna.tf32.f32 %0, %1;" : "=r"(u) : "f"(x));
    return __uint_as_float(u);
}

__device__ __forceinline__ void sts4_tf32(float* p, float4 v) {
    float4 o;
    o.x = tf32r(v.x); o.y = tf32r(v.y); o.z = tf32r(v.z); o.w = tf32r(v.w);
    *(float4*)p = o;
}

__device__ __forceinline__ void mma8(float* c, const float* a, const float* b) {
    uint32_t A0 = __float_as_uint(a[0]), A1 = __float_as_uint(a[1]);
    uint32_t A2 = __float_as_uint(a[2]), A3 = __float_as_uint(a[3]);
    uint32_t B0 = __float_as_uint(b[0]), B1 = __float_as_uint(b[1]);
    asm volatile(
        "mma.sync.aligned.m16n8k8.row.col.f32.tf32.tf32.f32 "
        "{%0,%1,%2,%3}, {%4,%5,%6,%7}, {%8,%9}, {%0,%1,%2,%3};\n"
        : "+f"(c[0]), "+f"(c[1]), "+f"(c[2]), "+f"(c[3])
        : "r"(A0), "r"(A1), "r"(A2), "r"(A3), "r"(B0), "r"(B1));
}

// ---------------- LayerNorm: one block per row, 256 threads --------------------
__global__ void __launch_bounds__(256) ln_kernel(const float* __restrict__ x,
                                                 const float* __restrict__ g,
                                                 const float* __restrict__ b,
                                                 float* __restrict__ out) {
    int row = blockIdx.x;
    const float4* xr = (const float4*)(x + (size_t)row * DD);
    float4 t = xr[threadIdx.x];
    float s  = t.x + t.y + t.z + t.w;
    float sq = t.x*t.x + t.y*t.y + t.z*t.z + t.w*t.w;
    __shared__ float rs[8], rq[8];
    for (int o = 16; o; o >>= 1) {
        s  += __shfl_down_sync(0xffffffffu, s,  o);
        sq += __shfl_down_sync(0xffffffffu, sq, o);
    }
    int wid = threadIdx.x >> 5, lane = threadIdx.x & 31;
    if (lane == 0) { rs[wid] = s; rq[wid] = sq; }
    __syncthreads();
    if (threadIdx.x == 0) {
        float a = 0.f, c = 0.f;
        for (int i = 0; i < 8; i++) { a += rs[i]; c += rq[i]; }
        rs[0] = a; rq[0] = c;
    }
    __syncthreads();
    float mean = rs[0] * (1.f / DD);
    float var  = rq[0] * (1.f / DD) - mean * mean;
    float rstd = rsqrtf(var + 1e-5f);
    float4 gg = ((const float4*)g)[threadIdx.x];
    float4 bb = ((const float4*)b)[threadIdx.x];
    float4 o4;
    o4.x = (t.x - mean) * rstd * gg.x + bb.x;
    o4.y = (t.y - mean) * rstd * gg.y + bb.y;
    o4.z = (t.z - mean) * rstd * gg.z + bb.z;
    o4.w = (t.w - mean) * rstd * gg.w + bb.w;
    ((float4*)(out + (size_t)row * DD))[threadIdx.x] = o4;
}

// ---------------- routing v5: 4 tok x 4 exp, TWO 128-wide D chunks per block ---
// grid (TT/16, 4). Block accumulates chunks y and y+4; lgp has 4 chunk slots.
__global__ void __launch_bounds__(256) route5_kernel(
    const float* __restrict__ nx,
    const float* __restrict__ W0, const float* __restrict__ W1,
    const float* __restrict__ W2, const float* __restrict__ W3,
    int nE, float* __restrict__ lgp) {
    __shared__ float xs[16 * 132];
    __shared__ float ws[64 * 132];   // reused as partials [4][16][68] after compute
    int tid = threadIdx.x;
    int tok0 = blockIdx.x * 16;
    int dq = tid >> 6, tg = (tid >> 4) & 3, eg = tid & 15;
    const float* Ws[4] = {W0, W1, W2, W3};
    bool em[4];
#pragma unroll
    for (int i = 0; i < 4; i++) em[i] = (eg + i * 16) < nE;
    float a[4][4];
#pragma unroll
    for (int j = 0; j < 4; j++)
#pragma unroll
        for (int i = 0; i < 4; i++) a[j][i] = 0.f;

#pragma unroll
    for (int ci = 0; ci < 2; ci++) {
        int c = blockIdx.y + ci * 4;
        __syncthreads();
#pragma unroll
        for (int i = 0; i < 2; i++) {
            int f = tid + 256 * i;
            int tt = f >> 5, d4 = f & 31;
            *(float4*)&xs[tt * 132 + d4 * 4] =
                *(const float4*)(nx + (size_t)(tok0 + tt) * DD + c * 128 + d4 * 4);
        }
#pragma unroll
        for (int i = 0; i < 8; i++) {
            int f = tid + 256 * i;
            if (f < nE * 32) {
                int e = f >> 5, d4 = f & 31;
                const float* src = Ws[e >> 4] + (size_t)(e & 15) * DD + c * 128 + d4 * 4;
                *(float4*)&ws[e * 132 + d4 * 4] = *(const float4*)src;
            }
        }
        __syncthreads();
#pragma unroll
        for (int d4 = dq * 8; d4 < dq * 8 + 8; d4++) {
            float4 xv[4], wv[4];
#pragma unroll
            for (int j = 0; j < 4; j++)
                xv[j] = *(float4*)&xs[(tg * 4 + j) * 132 + d4 * 4];
#pragma unroll
            for (int i = 0; i < 4; i++)
                wv[i] = em[i] ? *(float4*)&ws[(eg + i * 16) * 132 + d4 * 4]
                              : make_float4(0.f, 0.f, 0.f, 0.f);
#pragma unroll
            for (int j = 0; j < 4; j++)
#pragma unroll
                for (int i = 0; i < 4; i++)
                    a[j][i] += xv[j].x * wv[i].x + xv[j].y * wv[i].y +
                               xv[j].z * wv[i].z + xv[j].w * wv[i].w;
        }
    }
    __syncthreads();
    float* part = ws;     // [dq][t(16)][68]
#pragma unroll
    for (int j = 0; j < 4; j++)
#pragma unroll
        for (int i = 0; i < 4; i++)
            part[dq * 1088 + (tg * 4 + j) * 68 + eg + i * 16] = a[j][i];
    __syncthreads();
    {
        int t = tid >> 4, e0 = (tid * 4) & 63;
        float4 s = make_float4(0.f, 0.f, 0.f, 0.f);
#pragma unroll
        for (int d = 0; d < 4; d++) {
            float4 p = *(float4*)&part[d * 1088 + t * 68 + e0];
            s.x += p.x; s.y += p.y; s.z += p.z; s.w += p.w;
        }
        *(float4*)&lgp[((size_t)blockIdx.y * TT + tok0 + t) * 64 + e0] = s;
    }
}

// pool partials: sum 4 chunks, softmax in 16-expert segments, pooled accumulate.
__global__ void __launch_bounds__(256) pool3_kernel(
    const float* __restrict__ lgp, const float* __restrict__ imp,
    int nW, float* __restrict__ wacc) {
    int tid = threadIdx.x;
    int t = tid >> 6, e = tid & 63;
    int tok = blockIdx.x * 4 + t;
    float l = 0.f;
#pragma unroll
    for (int c = 0; c < 4; c++)
        l += lgp[((size_t)c * TT + tok) * 64 + e];
    float mx = l;
#pragma unroll
    for (int o = 1; o < 16; o <<= 1)
        mx = fmaxf(mx, __shfl_xor_sync(0xffffffffu, mx, o));
    float ev = __expf(l - mx);
    float s = ev;
#pragma unroll
    for (int o = 1; o < 16; o <<= 1)
        s += __shfl_xor_sync(0xffffffffu, s, o);
    if (e < nW * NEXP) {
        int r = e >> 4, n = e & 15, b = tok / SS;
        atomicAdd(&wacc[(r * BB + b) * NEXP + n], imp[tok] * ev / s);
    }
}

__global__ void norm_kernel(float* w, int cnt) {
    int i = threadIdx.x;
    if (i < cnt) {
        float* p = w + i * NEXP;
        float s = 0.f;
        for (int n = 0; n < NEXP; n++) s += p[n];
        float inv = 1.f / (s + 1e-8f);
        for (int n = 0; n < NEXP; n++) p[n] *= inv;
    }
}

// ---------------- pool mixes: both batches per thread (pool read once) ---------
// grid 2048: blocks [0,1024) -> sc (CN), [1024,2048) -> eq/ek/ev (EP).
__global__ void __launch_bounds__(256) mixfused2_kernel(
    const float* __restrict__ w, const float* __restrict__ CN,
    const float* __restrict__ EP, float* __restrict__ sc,
    float* __restrict__ eq, float* __restrict__ ek, float* __restrict__ ev) {
    const size_t X = (size_t)DD * RR;
    if (blockIdx.x < 1024) {
        size_t r = (size_t)blockIdx.x * 256 + threadIdx.x;
        float a0 = 0.f, a1 = 0.f;
#pragma unroll
        for (int n = 0; n < NEXP; n++) {
            float p = CN[(size_t)n * X + r];
            a0 += w[n] * p;
            a1 += w[16 + n] * p;
        }
        sc[r] = a0; sc[X + r] = a1;
    } else {
        size_t r = (size_t)(blockIdx.x - 1024) * 256 + threadIdx.x;
        float q0 = 0.f, q1 = 0.f, k0 = 0.f, k1 = 0.f, v0 = 0.f, v1 = 0.f;
#pragma unroll
        for (int n = 0; n < NEXP; n++) {
            float p = EP[(size_t)n * X + r];
            q0 += w[32 + n] * p; q1 += w[48 + n] * p;
            k0 += w[64 + n] * p; k1 += w[80 + n] * p;
            v0 += w[96 + n] * p; v1 += w[112 + n] * p;
        }
        eq[r] = q0; eq[X + r] = q1;
        ek[r] = k0; ek[X + r] = k1;
        ev[r] = v0; ev[X + r] = v1;
    }
}

// mc = wm . CN, both batches. grid 1024.
__global__ void __launch_bounds__(256) mix2_kernel(
    const float* __restrict__ wm, const float* __restrict__ CN,
    float* __restrict__ mc) {
    const size_t X = (size_t)DD * RR;
    size_t r = (size_t)blockIdx.x * 256 + threadIdx.x;
    float a0 = 0.f, a1 = 0.f;
#pragma unroll
    for (int n = 0; n < NEXP; n++) {
        float p = CN[(size_t)n * X + r];
        a0 += wm[n] * p;
        a1 += wm[16 + n] * p;
    }
    mc[r] = a0; mc[X + r] = a1;
}

// ---------------- tf32 tensor-core GEMM body: 128x128 block, BK=16 -------------
// lda/ldb = row strides (decoupled from K for split-K). OUTBF: bf16 C.
// ATOM: atomicAdd into pre-zeroed fp32 C.
template<bool TRANSB, bool RES, bool OUTBF, bool ATOM>
__device__ __forceinline__ void tgemm_body(
    const float* __restrict__ A, const float* __restrict__ B,
    const float* __restrict__ resp, void* __restrict__ Cv,
    int N, int K, int lda, int ldb, float alpha) {
    const int n0 = blockIdx.x * 128, m0 = blockIdx.y * 128;
    __shared__ float As[128 * 20];
    __shared__ float Bs[2560];
    int tid = threadIdx.x;
    int lane = tid & 31, w = tid >> 5;
    int wm = (w & 1) * 64, wn = (w >> 1) * 32;
    int lq = lane >> 2, lr = lane & 3;

    int rowA = tid >> 2, c4A = (tid & 3) * 4;
    const float* gA = A + (size_t)(m0 + rowA) * lda + c4A;
    float* sAp = &As[rowA * 20 + c4A];
    const float* gB;
    float* sBp;
    int gBstep, gBoff2, sBoff2;
    if (!TRANSB) {
        int rB = tid >> 5, cB = (tid & 31) * 4;
        gB = B + (size_t)rB * ldb + n0 + cB;
        sBp = &Bs[rB * 136 + cB];
        gBstep = 16 * ldb; gBoff2 = 8 * ldb; sBoff2 = 8 * 136;
    } else {
        int nB = tid >> 2, c4B = (tid & 3) * 4;
        gB = B + (size_t)(n0 + nB) * ldb + c4B;
        sBp = &Bs[nB * 20 + c4B];
        gBstep = 16; gBoff2 = 64 * ldb; sBoff2 = 64 * 20;
    }

    float acc[4][4][4];
#pragma unroll
    for (int mt = 0; mt < 4; mt++)
#pragma unroll
        for (int nt = 0; nt < 4; nt++)
#pragma unroll
            for (int i = 0; i < 4; i++) acc[mt][nt][i] = 0.f;

    float4 pa0 = *(const float4*)gA;
    float4 pa1 = *(const float4*)(gA + (size_t)64 * lda);
    float4 pb0 = *(const float4*)gB;
    float4 pb1 = *(const float4*)(gB + gBoff2);

    for (int kt = 0; kt < K; kt += 16) {
        sts4_tf32(sAp, pa0);
        sts4_tf32(sAp + 64 * 20, pa1);
        sts4_tf32(sBp, pb0);
        sts4_tf32(sBp + sBoff2, pb1);
        __syncthreads();
        if (kt + 16 < K) {
            gA += 16;
            pa0 = *(const float4*)gA;
            pa1 = *(const float4*)(gA + (size_t)64 * lda);
            gB += gBstep;
            pb0 = *(const float4*)gB;
            pb1 = *(const float4*)(gB + gBoff2);
        }
#pragma unroll
        for (int ks = 0; ks < 16; ks += 8) {
            float af[4][4], bf[4][2];
#pragma unroll
            for (int mt = 0; mt < 4; mt++) {
                int r = wm + mt * 16 + lq;
                af[mt][0] = As[r * 20 + ks + lr];
                af[mt][1] = As[(r + 8) * 20 + ks + lr];
                af[mt][2] = As[r * 20 + ks + lr + 4];
                af[mt][3] = As[(r + 8) * 20 + ks + lr + 4];
            }
#pragma unroll
            for (int nt = 0; nt < 4; nt++) {
                int cc = wn + nt * 8 + lq;
                if (!TRANSB) {
                    bf[nt][0] = Bs[(ks + lr) * 136 + cc];
                    bf[nt][1] = Bs[(ks + 4 + lr) * 136 + cc];
                } else {
                    bf[nt][0] = Bs[cc * 20 + ks + lr];
                    bf[nt][1] = Bs[cc * 20 + ks + 4 + lr];
                }
            }
#pragma unroll
            for (int mt = 0; mt < 4; mt++)
#pragma unroll
                for (int nt = 0; nt < 4; nt++)
                    mma8(acc[mt][nt], af[mt], bf[nt]);
        }
        __syncthreads();
    }
#pragma unroll
    for (int mt = 0; mt < 4; mt++) {
        int r = m0 + wm + mt * 16 + lq;
#pragma unroll
        for (int nt = 0; nt < 4; nt++) {
            int cc = n0 + wn + nt * 8 + 2 * lr;
            float2 v0 = make_float2(alpha * acc[mt][nt][0], alpha * acc[mt][nt][1]);
            float2 v1 = make_float2(alpha * acc[mt][nt][2], alpha * acc[mt][nt][3]);
            size_t o0 = (size_t)r * N + cc;
            size_t o1 = (size_t)(r + 8) * N + cc;
            if (OUTBF) {
                __nv_bfloat16* Cb = (__nv_bfloat16*)Cv;
                *(__nv_bfloat162*)(Cb + o0) = __floats2bfloat162_rn(v0.x, v0.y);
                *(__nv_bfloat162*)(Cb + o1) = __floats2bfloat162_rn(v1.x, v1.y);
            } else if (ATOM) {
                float* Cf = (float*)Cv;
                atomicAdd(Cf + o0, v0.x); atomicAdd(Cf + o0 + 1, v0.y);
                atomicAdd(Cf + o1, v1.x); atomicAdd(Cf + o1 + 1, v1.y);
            } else {
                float* Cf = (float*)Cv;
                if (RES) {
                    float2 r0 = *(const float2*)(resp + o0);
                    float2 r1 = *(const float2*)(resp + o1);
                    v0.x += r0.x; v0.y += r0.y;
                    v1.x += r1.x; v1.y += r1.y;
                }
                *(float2*)(Cf + o0) = v0;
                *(float2*)(Cf + o1) = v1;
            }
        }
    }
}

template<bool TRANSB, bool RES, bool OUTBF>
__global__ void __launch_bounds__(256, 2) tgemm_kernel(
    const float* __restrict__ A, const float* __restrict__ B,
    const float* __restrict__ resp, void* __restrict__ C,
    int N, int K, int lda, int ldb, float alpha,
    long sA, long sB, long sC, long sR) {
    A += (size_t)blockIdx.z * sA;
    B += (size_t)blockIdx.z * sB;
    if (OUTBF) C = (void*)((__nv_bfloat16*)C + (size_t)blockIdx.z * sC);
    else       C = (void*)((float*)C + (size_t)blockIdx.z * sC);
    if (RES) resp += (size_t)blockIdx.z * sR;
    tgemm_body<TRANSB, RES, OUTBF, false>(A, B, resp, C, N, K, lda, ldb, alpha);
}

// split-K (x2) NN GEMM with atomic epilogue. grid.z = b*2 + ks.
__global__ void __launch_bounds__(256, 2) splitk_kernel(
    const float* __restrict__ A, const float* __restrict__ B,
    float* __restrict__ C, int N, int Kh, int lda, int ldb,
    long sA, long sB, long sC) {
    int z = blockIdx.z;
    int b = z >> 1, ks = z & 1;
    A += (size_t)b * sA + (size_t)ks * Kh;
    B += (size_t)b * sB + (size_t)ks * Kh * ldb;
    C += (size_t)b * sC;
    tgemm_body<false, false, false, true>(A, B, nullptr, C, N, Kh, lda, ldb, 1.f);
}

// merged Q/K/V projection: grid.z = 6 (which = z>>1, b = z&1)
__global__ void __launch_bounds__(256, 2) qkv_kernel(
    const float* __restrict__ h,
    const float* __restrict__ eq, const float* __restrict__ ek,
    const float* __restrict__ ev,
    float* __restrict__ q, float* __restrict__ k, float* __restrict__ v) {
    int z = blockIdx.z;
    int b = z & 1, which = z >> 1;
    const float* B = (which == 0 ? eq : which == 1 ? ek : ev) + (size_t)b * RR * DD;
    float* C = (which == 0 ? q : which == 1 ? k : v) + (size_t)b * SS * DD;
    const float* A = h + (size_t)b * SS * RR;
    tgemm_body<false, false, false, false>(A, B, nullptr, C, DD, RR, RR, DD, 1.f);
}

// ---------------- tf32 tensor-core causal flash attention ----------------------
__global__ void __launch_bounds__(256, 2) fattn_kernel(
    const float* __restrict__ Q, const float* __restrict__ K,
    const float* __restrict__ V, float* __restrict__ O) {
    int b = blockIdx.z, h = blockIdx.y;
    int q0 = (gridDim.x - 1 - blockIdx.x) * 128;
    __shared__ float Ks[64 * 68];
    __shared__ float Vs[64 * 72];
    int tid = threadIdx.x, lane = tid & 31, w = tid >> 5;
    int lq = lane >> 2, lr = lane & 3;
    int wrow = q0 + w * 16;

    float qf[8][4];
    const float* Qb = Q + ((size_t)(b * SS + wrow)) * DD + h * DHD;
#pragma unroll
    for (int ks = 0; ks < 8; ks++) {
        qf[ks][0] = tf32r(0.125f * Qb[lq * DD + ks * 8 + lr]);
        qf[ks][1] = tf32r(0.125f * Qb[(lq + 8) * DD + ks * 8 + lr]);
        qf[ks][2] = tf32r(0.125f * Qb[lq * DD + ks * 8 + lr + 4]);
        qf[ks][3] = tf32r(0.125f * Qb[(lq + 8) * DD + ks * 8 + lr + 4]);
    }
    float of[8][4];
#pragma unroll
    for (int dt = 0; dt < 8; dt++) {
        of[dt][0] = 0.f; of[dt][1] = 0.f; of[dt][2] = 0.f; of[dt][3] = 0.f;
    }
    float m0 = -1e30f, m1 = -1e30f, l0 = 0.f, l1 = 0.f;

    int ntiles = q0 / 64 + 2;
    for (int ti = 0; ti < ntiles; ti++) {
        int j0 = ti * 64;
        __syncthreads();
#pragma unroll
        for (int i = 0; i < 4; i++) {
            int f = tid + 256 * i;
            int r = f >> 4, c4 = (f & 15) * 4;
            size_t goff = ((size_t)(b * SS + j0 + r)) * DD + h * DHD + c4;
            sts4_tf32(&Ks[r * 68 + c4], *(const float4*)(K + goff));
            sts4_tf32(&Vs[r * 72 + c4], *(const float4*)(V + goff));
        }
        __syncthreads();
        if (j0 > wrow + 15) continue;

        float sc[8][4];
#pragma unroll
        for (int nt = 0; nt < 8; nt++) {
            sc[nt][0] = 0.f; sc[nt][1] = 0.f; sc[nt][2] = 0.f; sc[nt][3] = 0.f;
        }
#pragma unroll
        for (int nt = 0; nt < 8; nt++)
#pragma unroll
            for (int ks = 0; ks < 8; ks++) {
                float bf[2];
                bf[0] = Ks[(nt * 8 + lq) * 68 + ks * 8 + lr];
                bf[1] = Ks[(nt * 8 + lq) * 68 + ks * 8 + lr + 4];
                mma8(sc[nt], qf[ks], bf);
            }
        if (j0 + 63 > wrow) {
            int r0 = wrow + lq, r1 = r0 + 8;
#pragma unroll
            for (int nt = 0; nt < 8; nt++) {
                int col = j0 + nt * 8 + 2 * lr;
                if (col > r0)     sc[nt][0] = -1e30f;
                if (col + 1 > r0) sc[nt][1] = -1e30f;
                if (col > r1)     sc[nt][2] = -1e30f;
                if (col + 1 > r1) sc[nt][3] = -1e30f;
            }
        }
        float mx0 = -1e30f, mx1 = -1e30f;
#pragma unroll
        for (int nt = 0; nt < 8; nt++) {
            mx0 = fmaxf(mx0, fmaxf(sc[nt][0], sc[nt][1]));
            mx1 = fmaxf(mx1, fmaxf(sc[nt][2], sc[nt][3]));
        }
        mx0 = fmaxf(mx0, __shfl_xor_sync(0xffffffffu, mx0, 1));
        mx0 = fmaxf(mx0, __shfl_xor_sync(0xffffffffu, mx0, 2));
        mx1 = fmaxf(mx1, __shfl_xor_sync(0xffffffffu, mx1, 1));
        mx1 = fmaxf(mx1, __shfl_xor_sync(0xffffffffu, mx1, 2));
        float mn0 = fmaxf(m0, mx0), mn1 = fmaxf(m1, mx1);
        float f0 = __expf(m0 - mn0), f1 = __expf(m1 - mn1);
        m0 = mn0; m1 = mn1;
        l0 *= f0; l1 *= f1;
#pragma unroll
        for (int dt = 0; dt < 8; dt++) {
            of[dt][0] *= f0; of[dt][1] *= f0;
            of[dt][2] *= f1; of[dt][3] *= f1;
        }
        float rs0 = 0.f, rs1 = 0.f;
#pragma unroll
        for (int nt = 0; nt < 8; nt++) {
            float p0 = tf32r(__expf(sc[nt][0] - m0));
            float p1 = tf32r(__expf(sc[nt][1] - m0));
            float p2 = tf32r(__expf(sc[nt][2] - m1));
            float p3 = tf32r(__expf(sc[nt][3] - m1));
            sc[nt][0] = p0; sc[nt][1] = p1; sc[nt][2] = p2; sc[nt][3] = p3;
            rs0 += p0 + p1; rs1 += p2 + p3;
        }
        rs0 += __shfl_xor_sync(0xffffffffu, rs0, 1);
        rs0 += __shfl_xor_sync(0xffffffffu, rs0, 2);
        rs1 += __shfl_xor_sync(0xffffffffu, rs1, 1);
        rs1 += __shfl_xor_sync(0xffffffffu, rs1, 2);
        l0 += rs0; l1 += rs1;
        int srcA = (lane & ~3) | (lr >> 1);
        int srcB = srcA | 2;
        bool odd = (lr & 1) != 0;
#pragma unroll
        for (int nt = 0; nt < 8; nt++) {
            float t00 = __shfl_sync(0xffffffffu, sc[nt][0], srcA);
            float t01 = __shfl_sync(0xffffffffu, sc[nt][1], srcA);
            float t02 = __shfl_sync(0xffffffffu, sc[nt][2], srcA);
            float t03 = __shfl_sync(0xffffffffu, sc[nt][3], srcA);
            float u00 = __shfl_sync(0xffffffffu, sc[nt][0], srcB);
            float u01 = __shfl_sync(0xffffffffu, sc[nt][1], srcB);
            float u02 = __shfl_sync(0xffffffffu, sc[nt][2], srcB);
            float u03 = __shfl_sync(0xffffffffu, sc[nt][3], srcB);
            float pa[4];
            pa[0] = odd ? t01 : t00;
            pa[1] = odd ? t03 : t02;
            pa[2] = odd ? u01 : u00;
            pa[3] = odd ? u03 : u02;
#pragma unroll
            for (int dt = 0; dt < 8; dt++) {
                float bf[2];
                bf[0] = Vs[(nt * 8 + lr) * 72 + dt * 8 + lq];
                bf[1] = Vs[(nt * 8 + lr + 4) * 72 + dt * 8 + lq];
                mma8(of[dt], pa, bf);
            }
        }
    }
    float inv0 = 1.f / l0, inv1 = 1.f / l1;
    float* Ob0 = O + ((size_t)(b * SS + wrow + lq)) * DD + h * DHD;
    float* Ob1 = Ob0 + (size_t)8 * DD;
#pragma unroll
    for (int dt = 0; dt < 8; dt++) {
        *(float2*)&Ob0[dt * 8 + 2 * lr] = make_float2(of[dt][0] * inv0, of[dt][1] * inv0);
        *(float2*)&Ob1[dt * 8 + 2 * lr] = make_float2(of[dt][2] * inv1, of[dt][3] * inv1);
    }
}

// ---------------- top-8 over bf16 scores + gather + residual -------------------
__global__ void __launch_bounds__(256) topk3_kernel(const __nv_bfloat16* __restrict__ ms,
                                                    const float* __restrict__ x1,
                                                    const float* __restrict__ KV,
                                                    float* __restrict__ out) {
    int token = blockIdx.x;
    int tid = threadIdx.x, w = tid >> 5, lane = tid & 31;
    const __nv_bfloat16* row = ms + (size_t)token * NKK;
    float r[16];
#pragma unroll
    for (int i = 0; i < 4; i++) {
        uint2 u = *(const uint2*)(row + w * 512 + i * 128 + lane * 4);
        float2 f01 = __bfloat1622float2(*(const __nv_bfloat162*)&u.x);
        float2 f23 = __bfloat1622float2(*(const __nv_bfloat162*)&u.y);
        r[i * 4 + 0] = f01.x; r[i * 4 + 1] = f01.y;
        r[i * 4 + 2] = f23.x; r[i * 4 + 3] = f23.y;
    }
    __shared__ float cv_s[64];
    __shared__ int   ci_s[64];
    __shared__ float tv[TK];
    __shared__ int   tix[TK];
    __shared__ float w8[TK];
    uint32_t taken = 0;
    for (int k = 0; k < TK; k++) {
        float bv = -1e30f; int bi = 0;
#pragma unroll
        for (int i = 0; i < 16; i++) {
            if (!((taken >> i) & 1u) && r[i] > bv) { bv = r[i]; bi = i; }
        }
        int mygi = w * 512 + (bi >> 2) * 128 + lane * 4 + (bi & 3);
        float rv = bv; int gi = mygi;
#pragma unroll
        for (int o = 16; o; o >>= 1) {
            float ov = __shfl_xor_sync(0xffffffffu, rv, o);
            int   oi = __shfl_xor_sync(0xffffffffu, gi, o);
            if (ov > rv || (ov == rv && oi < gi)) { rv = ov; gi = oi; }
        }
        if (gi == mygi) taken |= 1u << bi;
        if (lane == 0) { cv_s[w * 8 + k] = rv; ci_s[w * 8 + k] = gi; }
    }
    __syncthreads();
    if (w == 0) {
        float c0 = cv_s[lane], c1 = cv_s[lane + 32];
        int i0 = ci_s[lane], i1 = ci_s[lane + 32];
        uint32_t tk = 0;
        for (int k = 0; k < TK; k++) {
            float bv = -1e30f; int gi = 0x7fffffff; int sel = -1;
            if (!(tk & 1u)) { bv = c0; gi = i0; sel = 0; }
            if (!(tk & 2u) && (c1 > bv || (c1 == bv && i1 < gi))) {
                bv = c1; gi = i1; sel = 1;
            }
            float rv = bv; int g = gi;
#pragma unroll
            for (int o = 16; o; o >>= 1) {
                float ov = __shfl_xor_sync(0xffffffffu, rv, o);
                int   oi = __shfl_xor_sync(0xffffffffu, g, o);
                if (ov > rv || (ov == rv && oi < g)) { rv = ov; g = oi; }
            }
            if (sel >= 0 && g == gi) tk |= (sel ? 2u : 1u);
            if (lane == 0) { tv[k] = rv; tix[k] = g; }
        }
        if (lane == 0) {
            float mx = tv[0];
            float e[TK], s = 0.f;
            for (int k = 0; k < TK; k++) { e[k] = __expf(tv[k] - mx); s += e[k]; }
            float inv = 1.f / s;
            for (int k = 0; k < TK; k++) w8[k] = e[k] * inv;
        }
    }
    __syncthreads();
    {
        float4 acc = *(const float4*)(x1 + (size_t)token * DD + tid * 4);
#pragma unroll
        for (int k = 0; k < TK; k++) {
            float4 kv = *(const float4*)(KV + (size_t)tix[k] * DD + tid * 4);
            float wk = w8[k];
            acc.x += wk * kv.x; acc.y += wk * kv.y;
            acc.z += wk * kv.z; acc.w += wk * kv.w;
        }
        *(float4*)(out + (size_t)token * DD + tid * 4) = acc;
    }
}

// ---------------- driver --------------------------------------------------------
extern "C" void kernel_launch(void* const* d_in, const int* in_sizes, int n_in,
                              void* d_out, int out_size) {
    const float* x   = (const float*)d_in[0];
    const float* imp = (const float*)d_in[1];
    const float* Wc  = (const float*)d_in[2];
    const float* WQ  = (const float*)d_in[3];
    const float* WK  = (const float*)d_in[4];
    const float* WV  = (const float*)d_in[5];
    const float* Wm  = (const float*)d_in[6];
    const float* CN  = (const float*)d_in[7];
    const float* EP  = (const float*)d_in[8];
    const float* kK  = (const float*)d_in[9];
    const float* kV  = (const float*)d_in[10];
    const float* WO  = (const float*)d_in[11];
    const float* g1  = (const float*)d_in[12];
    const float* b1  = (const float*)d_in[13];
    const float* g2  = (const float*)d_in[14];
    const float* b2  = (const float*)d_in[15];
    float* out = (float*)d_out;

    float *nx, *nx2, *w, *wm, *sc, *mc, *h, *qm, *eq, *ek, *ev;
    float *q, *k, *v, *ao, *x1, *msb, *lgp;
    cudaGetSymbolAddress((void**)&nx,  g_nx);
    cudaGetSymbolAddress((void**)&nx2, g_nx2);
    cudaGetSymbolAddress((void**)&w,   g_w);
    cudaGetSymbolAddress((void**)&wm,  g_wm);
    cudaGetSymbolAddress((void**)&sc,  g_sc);
    cudaGetSymbolAddress((void**)&mc,  g_mc);
    cudaGetSymbolAddress((void**)&h,   g_h);
    cudaGetSymbolAddress((void**)&qm,  g_qm);
    cudaGetSymbolAddress((void**)&eq,  g_eq);
    cudaGetSymbolAddress((void**)&ek,  g_ek);
    cudaGetSymbolAddress((void**)&ev,  g_ev);
    cudaGetSymbolAddress((void**)&q,   g_q);
    cudaGetSymbolAddress((void**)&k,   g_k);
    cudaGetSymbolAddress((void**)&v,   g_v);
    cudaGetSymbolAddress((void**)&ao,  g_ao);
    cudaGetSymbolAddress((void**)&x1,  g_x1);
    cudaGetSymbolAddress((void**)&msb, g_ms);
    cudaGetSymbolAddress((void**)&lgp, g_lgp);

    const long SD = (long)SS * DD;
    const long DR = (long)DD * RR;
    const long SR = (long)SS * RR;
    const long SNK = (long)SS * NKK;

    // ---- attention sub-block ----
    ln_kernel<<<BB * SS, 256>>>(x, g1, b1, nx);
    zeroall_kernel<<<1024, 256>>>((float4*)h, (float4*)qm, w, wm);
    route5_kernel<<<dim3(TT / 16, 4), 256>>>(nx, Wc, WQ, WK, WV, 64, lgp);
    pool3_kernel<<<TT / 4, 256>>>(lgp, imp, 4, w);
    norm_kernel<<<1, 32>>>(w, 4 * BB);
    mixfused2_kernel<<<2048, 256>>>(w, CN, EP, sc, eq, ek, ev);
    // h = nx @ sc : split-K x2, 128 CTAs
    splitk_kernel<<<dim3(RR / 128, SS / 128, 4), 256>>>(
        nx, sc, h, RR, DD / 2, DD, RR, SD, DR, SR);
    qkv_kernel<<<dim3(DD / 128, SS / 128, 6), 256>>>(h, eq, ek, ev, q, k, v);
    fattn_kernel<<<dim3(SS / 128, HH, BB), 256>>>(q, k, v, ao);
    tgemm_kernel<true, true, false><<<dim3(DD / 128, (BB * SS) / 128, 1), 256>>>(
        ao, WO, x, x1, DD, DD, DD, DD, 1.f, 0, 0, 0, 0);

    // ---- memory sub-block ----
    ln_kernel<<<BB * SS, 256>>>(x1, g2, b2, nx2);
    route5_kernel<<<dim3(TT / 16, 4), 256>>>(nx2, Wm, Wm, Wm, Wm, 16, lgp);
    pool3_kernel<<<TT / 4, 256>>>(lgp, imp, 1, wm);
    norm_kernel<<<1, 32>>>(wm, BB);
    mix2_kernel<<<1024, 256>>>(wm, CN, mc);
    // Qm = nx2 @ mc : split-K x2
    splitk_kernel<<<dim3(RR / 128, SS / 128, 4), 256>>>(
        nx2, mc, qm, RR, DD / 2, DD, RR, SD, DR, SR);
    // ms = Qm @ kK^T / sqrt(256), bf16 out
    tgemm_kernel<true, false, true><<<dim3(NKK / 128, SS / 128, BB), 256>>>(
        qm, kK, nullptr, msb, NKK, RR, RR, RR, 0.0625f, SR, 0, SNK, 0);
    topk3_kernel<<<BB * SS, 256>>>((const __nv_bfloat16*)msb, x1, kV, out);
}

// round 10
// speedup vs baseline: 3.8310x; 1.1231x over previous
#include <cuda_runtime.h>
#include <cuda_bf16.h>
#include <cuda_fp16.h>
#include <math.h>
#include <stdint.h>

#define BB 2
#define SS 2048
#define DD 1024
#define HH 16
#define DHD 64
#define RR 256
#define NEXP 16
#define NKK 4096
#define TK 8
#define TT (BB*SS)

// ---------------- scratch (device globals; no allocation allowed) -------------
__device__ float g_nx [BB*SS*DD];
__device__ float g_nx2[BB*SS*DD];
__device__ float g_w  [4*BB*NEXP];
__device__ float g_wm [BB*NEXP];
__device__ float g_sc [BB*DD*RR];
__device__ float g_mc [BB*DD*RR];
__device__ float g_h  [BB*SS*RR];
__device__ float g_qm [BB*SS*RR];
__device__ float g_eq [BB*RR*DD];
__device__ float g_ek [BB*RR*DD];
__device__ float g_ev [BB*RR*DD];
__device__ float g_q  [BB*SS*DD];
__device__ float g_k  [BB*SS*DD];
__device__ float g_v  [BB*SS*DD];
__device__ float g_ao [BB*SS*DD];
__device__ float g_x1 [BB*SS*DD];
__device__ float g_ms [(size_t)BB*SS*NKK];   // used as fp16 (half capacity)
__device__ float g_lgp[(size_t)TT*64];       // compact pooled logits

// ---------------- utility ------------------------------------------------------
// zero h, qm (1M floats each), lgp (256K), w/wm. grid 1024 x 256.
__global__ void __launch_bounds__(256) zeroall_kernel(float4* h4, float4* q4,
                                                      float4* lgp4,
                                                      float* w, float* wm) {
    int i = blockIdx.x * 256 + threadIdx.x;
    float4 z = make_float4(0.f, 0.f, 0.f, 0.f);
    h4[i] = z; q4[i] = z;
    if (blockIdx.x < 256) lgp4[i] = z;
    if (blockIdx.x == 0) {
        if (threadIdx.x < 128) w[threadIdx.x] = 0.f;
        else if (threadIdx.x < 160) wm[threadIdx.x - 128] = 0.f;
    }
}

__device__ __forceinline__ float tf32r(float x) {
    uint32_t u;
    asm("cvt.rna.tf32.f32 %0, %1;" : "=r"(u) : "f"(x));
    return __uint_as_float(u);
}

__device__ __forceinline__ void sts4_tf32(float* p, float4 v) {
    float4 o;
    o.x = tf32r(v.x); o.y = tf32r(v.y); o.z = tf32r(v.z); o.w = tf32r(v.w);
    *(float4*)p = o;
}

__device__ __forceinline__ void mma8(float* c, const float* a, const float* b) {
    uint32_t A0 = __float_as_uint(a[0]), A1 = __float_as_uint(a[1]);
    uint32_t A2 = __float_as_uint(a[2]), A3 = __float_as_uint(a[3]);
    uint32_t B0 = __float_as_uint(b[0]), B1 = __float_as_uint(b[1]);
    asm volatile(
        "mma.sync.aligned.m16n8k8.row.col.f32.tf32.tf32.f32 "
        "{%0,%1,%2,%3}, {%4,%5,%6,%7}, {%8,%9}, {%0,%1,%2,%3};\n"
        : "+f"(c[0]), "+f"(c[1]), "+f"(c[2]), "+f"(c[3])
        : "r"(A0), "r"(A1), "r"(A2), "r"(A3), "r"(B0), "r"(B1));
}

__device__ __forceinline__ void mma16(float* c, const uint32_t* a, const uint32_t* b) {
    asm volatile(
        "mma.sync.aligned.m16n8k16.row.col.f32.f16.f16.f32 "
        "{%0,%1,%2,%3}, {%4,%5,%6,%7}, {%8,%9}, {%0,%1,%2,%3};\n"
        : "+f"(c[0]), "+f"(c[1]), "+f"(c[2]), "+f"(c[3])
        : "r"(a[0]), "r"(a[1]), "r"(a[2]), "r"(a[3]), "r"(b[0]), "r"(b[1]));
}

// ---------------- LayerNorm: one block per row, 256 threads --------------------
__global__ void __launch_bounds__(256) ln_kernel(const float* __restrict__ x,
                                                 const float* __restrict__ g,
                                                 const float* __restrict__ b,
                                                 float* __restrict__ out) {
    int row = blockIdx.x;
    const float4* xr = (const float4*)(x + (size_t)row * DD);
    float4 t = xr[threadIdx.x];
    float s  = t.x + t.y + t.z + t.w;
    float sq = t.x*t.x + t.y*t.y + t.z*t.z + t.w*t.w;
    __shared__ float rs[8], rq[8];
    for (int o = 16; o; o >>= 1) {
        s  += __shfl_down_sync(0xffffffffu, s,  o);
        sq += __shfl_down_sync(0xffffffffu, sq, o);
    }
    int wid = threadIdx.x >> 5, lane = threadIdx.x & 31;
    if (lane == 0) { rs[wid] = s; rq[wid] = sq; }
    __syncthreads();
    if (threadIdx.x == 0) {
        float a = 0.f, c = 0.f;
        for (int i = 0; i < 8; i++) { a += rs[i]; c += rq[i]; }
        rs[0] = a; rq[0] = c;
    }
    __syncthreads();
    float mean = rs[0] * (1.f / DD);
    float var  = rq[0] * (1.f / DD) - mean * mean;
    float rstd = rsqrtf(var + 1e-5f);
    float4 gg = ((const float4*)g)[threadIdx.x];
    float4 bb = ((const float4*)b)[threadIdx.x];
    float4 o4;
    o4.x = (t.x - mean) * rstd * gg.x + bb.x;
    o4.y = (t.y - mean) * rstd * gg.y + bb.y;
    o4.z = (t.z - mean) * rstd * gg.z + bb.z;
    o4.w = (t.w - mean) * rstd * gg.w + bb.w;
    ((float4*)(out + (size_t)row * DD))[threadIdx.x] = o4;
}

// ---------------- routing v6: 4 tok x 4 exp, 2 chunks/block, atomic pool -------
// grid (TT/16, 4). Block accumulates chunks y and y+4, atomicAdds into compact
// lgp[token][64] (pre-zeroed; pool4 clears after read for next pass/replay).
__global__ void __launch_bounds__(256) route6_kernel(
    const float* __restrict__ nx,
    const float* __restrict__ W0, const float* __restrict__ W1,
    const float* __restrict__ W2, const float* __restrict__ W3,
    int nE, float* __restrict__ lgp) {
    __shared__ float xs[16 * 132];
    __shared__ float ws[64 * 132];   // reused as partials [4][16][68]
    int tid = threadIdx.x;
    int tok0 = blockIdx.x * 16;
    int dq = tid >> 6, tg = (tid >> 4) & 3, eg = tid & 15;
    const float* Ws[4] = {W0, W1, W2, W3};
    bool em[4];
#pragma unroll
    for (int i = 0; i < 4; i++) em[i] = (eg + i * 16) < nE;
    float a[4][4];
#pragma unroll
    for (int j = 0; j < 4; j++)
#pragma unroll
        for (int i = 0; i < 4; i++) a[j][i] = 0.f;

#pragma unroll
    for (int ci = 0; ci < 2; ci++) {
        int c = blockIdx.y + ci * 4;
        __syncthreads();
#pragma unroll
        for (int i = 0; i < 2; i++) {
            int f = tid + 256 * i;
            int tt = f >> 5, d4 = f & 31;
            *(float4*)&xs[tt * 132 + d4 * 4] =
                *(const float4*)(nx + (size_t)(tok0 + tt) * DD + c * 128 + d4 * 4);
        }
#pragma unroll
        for (int i = 0; i < 8; i++) {
            int f = tid + 256 * i;
            if (f < nE * 32) {
                int e = f >> 5, d4 = f & 31;
                const float* src = Ws[e >> 4] + (size_t)(e & 15) * DD + c * 128 + d4 * 4;
                *(float4*)&ws[e * 132 + d4 * 4] = *(const float4*)src;
            }
        }
        __syncthreads();
#pragma unroll
        for (int d4 = dq * 8; d4 < dq * 8 + 8; d4++) {
            float4 xv[4], wv[4];
#pragma unroll
            for (int j = 0; j < 4; j++)
                xv[j] = *(float4*)&xs[(tg * 4 + j) * 132 + d4 * 4];
#pragma unroll
            for (int i = 0; i < 4; i++)
                wv[i] = em[i] ? *(float4*)&ws[(eg + i * 16) * 132 + d4 * 4]
                              : make_float4(0.f, 0.f, 0.f, 0.f);
#pragma unroll
            for (int j = 0; j < 4; j++)
#pragma unroll
                for (int i = 0; i < 4; i++)
                    a[j][i] += xv[j].x * wv[i].x + xv[j].y * wv[i].y +
                               xv[j].z * wv[i].z + xv[j].w * wv[i].w;
        }
    }
    __syncthreads();
    float* part = ws;     // [dq][t(16)][68]
#pragma unroll
    for (int j = 0; j < 4; j++)
#pragma unroll
        for (int i = 0; i < 4; i++)
            part[dq * 1088 + (tg * 4 + j) * 68 + eg + i * 16] = a[j][i];
    __syncthreads();
    {
        int t = tid >> 4, e0 = (tid * 4) & 63;
        float4 s = make_float4(0.f, 0.f, 0.f, 0.f);
#pragma unroll
        for (int d = 0; d < 4; d++) {
            float4 p = *(float4*)&part[d * 1088 + t * 68 + e0];
            s.x += p.x; s.y += p.y; s.z += p.z; s.w += p.w;
        }
        float* dst = &lgp[(size_t)(tok0 + t) * 64 + e0];
        atomicAdd(dst + 0, s.x);
        atomicAdd(dst + 1, s.y);
        atomicAdd(dst + 2, s.z);
        atomicAdd(dst + 3, s.w);
    }
}

// pool compact logits: softmax in 16-expert segments, pooled accumulate.
// Clears lgp after reading (ready for next routing pass / graph replay).
__global__ void __launch_bounds__(256) pool4_kernel(
    float* __restrict__ lgp, const float* __restrict__ imp,
    int nW, float* __restrict__ wacc) {
    int tid = threadIdx.x;
    int t = tid >> 6, e = tid & 63;
    int tok = blockIdx.x * 4 + t;
    size_t idx = (size_t)tok * 64 + e;
    float l = lgp[idx];
    lgp[idx] = 0.f;
    float mx = l;
#pragma unroll
    for (int o = 1; o < 16; o <<= 1)
        mx = fmaxf(mx, __shfl_xor_sync(0xffffffffu, mx, o));
    float ev = __expf(l - mx);
    float s = ev;
#pragma unroll
    for (int o = 1; o < 16; o <<= 1)
        s += __shfl_xor_sync(0xffffffffu, s, o);
    if (e < nW * NEXP) {
        int r = e >> 4, n = e & 15, b = tok / SS;
        atomicAdd(&wacc[(r * BB + b) * NEXP + n], imp[tok] * ev / s);
    }
}

__global__ void norm_kernel(float* w, int cnt) {
    int i = threadIdx.x;
    if (i < cnt) {
        float* p = w + i * NEXP;
        float s = 0.f;
        for (int n = 0; n < NEXP; n++) s += p[n];
        float inv = 1.f / (s + 1e-8f);
        for (int n = 0; n < NEXP; n++) p[n] *= inv;
    }
}

// ---------------- pool mixes: both batches per thread (pool read once) ---------
__global__ void __launch_bounds__(256) mixfused2_kernel(
    const float* __restrict__ w, const float* __restrict__ CN,
    const float* __restrict__ EP, float* __restrict__ sc,
    float* __restrict__ eq, float* __restrict__ ek, float* __restrict__ ev) {
    const size_t X = (size_t)DD * RR;
    if (blockIdx.x < 1024) {
        size_t r = (size_t)blockIdx.x * 256 + threadIdx.x;
        float a0 = 0.f, a1 = 0.f;
#pragma unroll
        for (int n = 0; n < NEXP; n++) {
            float p = CN[(size_t)n * X + r];
            a0 += w[n] * p;
            a1 += w[16 + n] * p;
        }
        sc[r] = a0; sc[X + r] = a1;
    } else {
        size_t r = (size_t)(blockIdx.x - 1024) * 256 + threadIdx.x;
        float q0 = 0.f, q1 = 0.f, k0 = 0.f, k1 = 0.f, v0 = 0.f, v1 = 0.f;
#pragma unroll
        for (int n = 0; n < NEXP; n++) {
            float p = EP[(size_t)n * X + r];
            q0 += w[32 + n] * p; q1 += w[48 + n] * p;
            k0 += w[64 + n] * p; k1 += w[80 + n] * p;
            v0 += w[96 + n] * p; v1 += w[112 + n] * p;
        }
        eq[r] = q0; eq[X + r] = q1;
        ek[r] = k0; ek[X + r] = k1;
        ev[r] = v0; ev[X + r] = v1;
    }
}

__global__ void __launch_bounds__(256) mix2_kernel(
    const float* __restrict__ wm, const float* __restrict__ CN,
    float* __restrict__ mc) {
    const size_t X = (size_t)DD * RR;
    size_t r = (size_t)blockIdx.x * 256 + threadIdx.x;
    float a0 = 0.f, a1 = 0.f;
#pragma unroll
    for (int n = 0; n < NEXP; n++) {
        float p = CN[(size_t)n * X + r];
        a0 += wm[n] * p;
        a1 += wm[16 + n] * p;
    }
    mc[r] = a0; mc[X + r] = a1;
}

// ---------------- tf32 tensor-core GEMM body (NN path) -------------------------
template<bool TRANSB, bool RES, bool ATOM>
__device__ __forceinline__ void tgemm_body(
    const float* __restrict__ A, const float* __restrict__ B,
    const float* __restrict__ resp, float* __restrict__ Cf,
    int N, int K, int lda, int ldb, float alpha) {
    const int n0 = blockIdx.x * 128, m0 = blockIdx.y * 128;
    __shared__ float As[128 * 20];
    __shared__ float Bs[2560];
    int tid = threadIdx.x;
    int lane = tid & 31, w = tid >> 5;
    int wm = (w & 1) * 64, wn = (w >> 1) * 32;
    int lq = lane >> 2, lr = lane & 3;

    int rowA = tid >> 2, c4A = (tid & 3) * 4;
    const float* gA = A + (size_t)(m0 + rowA) * lda + c4A;
    float* sAp = &As[rowA * 20 + c4A];
    const float* gB;
    float* sBp;
    int gBstep, gBoff2, sBoff2;
    if (!TRANSB) {
        int rB = tid >> 5, cB = (tid & 31) * 4;
        gB = B + (size_t)rB * ldb + n0 + cB;
        sBp = &Bs[rB * 136 + cB];
        gBstep = 16 * ldb; gBoff2 = 8 * ldb; sBoff2 = 8 * 136;
    } else {
        int nB = tid >> 2, c4B = (tid & 3) * 4;
        gB = B + (size_t)(n0 + nB) * ldb + c4B;
        sBp = &Bs[nB * 20 + c4B];
        gBstep = 16; gBoff2 = 64 * ldb; sBoff2 = 64 * 20;
    }

    float acc[4][4][4];
#pragma unroll
    for (int mt = 0; mt < 4; mt++)
#pragma unroll
        for (int nt = 0; nt < 4; nt++)
#pragma unroll
            for (int i = 0; i < 4; i++) acc[mt][nt][i] = 0.f;

    float4 pa0 = *(const float4*)gA;
    float4 pa1 = *(const float4*)(gA + (size_t)64 * lda);
    float4 pb0 = *(const float4*)gB;
    float4 pb1 = *(const float4*)(gB + gBoff2);

    for (int kt = 0; kt < K; kt += 16) {
        sts4_tf32(sAp, pa0);
        sts4_tf32(sAp + 64 * 20, pa1);
        sts4_tf32(sBp, pb0);
        sts4_tf32(sBp + sBoff2, pb1);
        __syncthreads();
        if (kt + 16 < K) {
            gA += 16;
            pa0 = *(const float4*)gA;
            pa1 = *(const float4*)(gA + (size_t)64 * lda);
            gB += gBstep;
            pb0 = *(const float4*)gB;
            pb1 = *(const float4*)(gB + gBoff2);
        }
#pragma unroll
        for (int ks = 0; ks < 16; ks += 8) {
            float af[4][4], bf[4][2];
#pragma unroll
            for (int mt = 0; mt < 4; mt++) {
                int r = wm + mt * 16 + lq;
                af[mt][0] = As[r * 20 + ks + lr];
                af[mt][1] = As[(r + 8) * 20 + ks + lr];
                af[mt][2] = As[r * 20 + ks + lr + 4];
                af[mt][3] = As[(r + 8) * 20 + ks + lr + 4];
            }
#pragma unroll
            for (int nt = 0; nt < 4; nt++) {
                int cc = wn + nt * 8 + lq;
                if (!TRANSB) {
                    bf[nt][0] = Bs[(ks + lr) * 136 + cc];
                    bf[nt][1] = Bs[(ks + 4 + lr) * 136 + cc];
                } else {
                    bf[nt][0] = Bs[cc * 20 + ks + lr];
                    bf[nt][1] = Bs[cc * 20 + ks + 4 + lr];
                }
            }
#pragma unroll
            for (int mt = 0; mt < 4; mt++)
#pragma unroll
                for (int nt = 0; nt < 4; nt++)
                    mma8(acc[mt][nt], af[mt], bf[nt]);
        }
        __syncthreads();
    }
#pragma unroll
    for (int mt = 0; mt < 4; mt++) {
        int r = m0 + wm + mt * 16 + lq;
#pragma unroll
        for (int nt = 0; nt < 4; nt++) {
            int cc = n0 + wn + nt * 8 + 2 * lr;
            float2 v0 = make_float2(alpha * acc[mt][nt][0], alpha * acc[mt][nt][1]);
            float2 v1 = make_float2(alpha * acc[mt][nt][2], alpha * acc[mt][nt][3]);
            size_t o0 = (size_t)r * N + cc;
            size_t o1 = (size_t)(r + 8) * N + cc;
            if (ATOM) {
                atomicAdd(Cf + o0, v0.x); atomicAdd(Cf + o0 + 1, v0.y);
                atomicAdd(Cf + o1, v1.x); atomicAdd(Cf + o1 + 1, v1.y);
            } else {
                if (RES) {
                    float2 r0 = *(const float2*)(resp + o0);
                    float2 r1 = *(const float2*)(resp + o1);
                    v0.x += r0.x; v0.y += r0.y;
                    v1.x += r1.x; v1.y += r1.y;
                }
                *(float2*)(Cf + o0) = v0;
                *(float2*)(Cf + o1) = v1;
            }
        }
    }
}

// split-K (x2) NN GEMM with atomic epilogue. grid.z = b*2 + ks.
__global__ void __launch_bounds__(256, 2) splitk_kernel(
    const float* __restrict__ A, const float* __restrict__ B,
    float* __restrict__ C, int N, int Kh, int lda, int ldb,
    long sA, long sB, long sC) {
    int z = blockIdx.z;
    int b = z >> 1, ks = z & 1;
    A += (size_t)b * sA + (size_t)ks * Kh;
    B += (size_t)b * sB + (size_t)ks * Kh * ldb;
    C += (size_t)b * sC;
    tgemm_body<false, false, true>(A, B, nullptr, C, N, Kh, lda, ldb, 1.f);
}

// merged Q/K/V projection: grid.z = 6 (which = z>>1, b = z&1)
__global__ void __launch_bounds__(256, 2) qkv_kernel(
    const float* __restrict__ h,
    const float* __restrict__ eq, const float* __restrict__ ek,
    const float* __restrict__ ev,
    float* __restrict__ q, float* __restrict__ k, float* __restrict__ v) {
    int z = blockIdx.z;
    int b = z & 1, which = z >> 1;
    const float* B = (which == 0 ? eq : which == 1 ? ek : ev) + (size_t)b * RR * DD;
    float* C = (which == 0 ? q : which == 1 ? k : v) + (size_t)b * SS * DD;
    const float* A = h + (size_t)b * SS * RR;
    tgemm_body<false, false, false>(A, B, nullptr, C, DD, RR, RR, DD, 1.f);
}

// ---------------- fp16 m16n8k16 NT GEMM: 128x128 tile, BK=32 -------------------
// A [M,K] fp32, B [N,K] fp32 (both k-contiguous), converted to fp16 at staging.
// fp16 eps == tf32 eps (10-bit mantissa) -> accuracy-neutral vs tf32.
template<bool RES, bool OUTHALF>
__global__ void __launch_bounds__(256, 2) hgemm_nt_kernel(
    const float* __restrict__ A, const float* __restrict__ B,
    const float* __restrict__ resp, void* __restrict__ Cv,
    int N, int K, int lda, int ldb, float alpha,
    long sA, long sB, long sC, long sR) {
    A += (size_t)blockIdx.z * sA;
    B += (size_t)blockIdx.z * sB;
    __half* Ch = (__half*)Cv;
    float* Cf = (float*)Cv;
    if (OUTHALF) Ch += (size_t)blockIdx.z * sC;
    else         Cf += (size_t)blockIdx.z * sC;
    if (RES) resp += (size_t)blockIdx.z * sR;
    const int n0 = blockIdx.x * 128, m0 = blockIdx.y * 128;
    __shared__ uint32_t AsW[128 * 20];   // [row][k-pairs], 16 data + 4 pad words
    __shared__ uint32_t BsW[128 * 20];
    int tid = threadIdx.x, lane = tid & 31, w = tid >> 5;
    int wm = (w & 1) * 64, wn = (w >> 1) * 32;
    int lq = lane >> 2, lr = lane & 3;
    int row = tid >> 3, c4 = tid & 7;    // row 0-31, float4 index within 32 k-vals

    const float* gA = A + (size_t)(m0 + row) * lda + c4 * 4;
    const float* gB = B + (size_t)(n0 + row) * ldb + c4 * 4;
    float4 pa[4], pb[4];
#pragma unroll
    for (int i = 0; i < 4; i++) {
        pa[i] = *(const float4*)(gA + (size_t)(32 * i) * lda);
        pb[i] = *(const float4*)(gB + (size_t)(32 * i) * ldb);
    }

    float acc[4][4][4];
#pragma unroll
    for (int mt = 0; mt < 4; mt++)
#pragma unroll
        for (int nt = 0; nt < 4; nt++)
#pragma unroll
            for (int i = 0; i < 4; i++) acc[mt][nt][i] = 0.f;

    for (int kt = 0; kt < K; kt += 32) {
#pragma unroll
        for (int i = 0; i < 4; i++) {
            __half2 h0 = __floats2half2_rn(pa[i].x, pa[i].y);
            __half2 h1 = __floats2half2_rn(pa[i].z, pa[i].w);
            uint2 ua;
            ua.x = *(uint32_t*)&h0; ua.y = *(uint32_t*)&h1;
            *(uint2*)&AsW[(row + 32 * i) * 20 + c4 * 2] = ua;
            __half2 g0 = __floats2half2_rn(pb[i].x, pb[i].y);
            __half2 g1 = __floats2half2_rn(pb[i].z, pb[i].w);
            uint2 ub;
            ub.x = *(uint32_t*)&g0; ub.y = *(uint32_t*)&g1;
            *(uint2*)&BsW[(row + 32 * i) * 20 + c4 * 2] = ub;
        }
        __syncthreads();
        if (kt + 32 < K) {
            gA += 32; gB += 32;
#pragma unroll
            for (int i = 0; i < 4; i++) {
                pa[i] = *(const float4*)(gA + (size_t)(32 * i) * lda);
                pb[i] = *(const float4*)(gB + (size_t)(32 * i) * ldb);
            }
        }
#pragma unroll
        for (int ks = 0; ks < 2; ks++) {
            uint32_t af[4][4], bf[4][2];
#pragma unroll
            for (int mt = 0; mt < 4; mt++) {
                int r = wm + mt * 16 + lq;
                af[mt][0] = AsW[r * 20 + ks * 8 + lr];
                af[mt][1] = AsW[(r + 8) * 20 + ks * 8 + lr];
                af[mt][2] = AsW[r * 20 + ks * 8 + 4 + lr];
                af[mt][3] = AsW[(r + 8) * 20 + ks * 8 + 4 + lr];
            }
#pragma unroll
            for (int nt = 0; nt < 4; nt++) {
                int cc = wn + nt * 8 + lq;
                bf[nt][0] = BsW[cc * 20 + ks * 8 + lr];
                bf[nt][1] = BsW[cc * 20 + ks * 8 + 4 + lr];
            }
#pragma unroll
            for (int mt = 0; mt < 4; mt++)
#pragma unroll
                for (int nt = 0; nt < 4; nt++)
                    mma16(acc[mt][nt], af[mt], bf[nt]);
        }
        __syncthreads();
    }
#pragma unroll
    for (int mt = 0; mt < 4; mt++) {
        int r = m0 + wm + mt * 16 + lq;
#pragma unroll
        for (int nt = 0; nt < 4; nt++) {
            int cc = n0 + wn + nt * 8 + 2 * lr;
            float2 v0 = make_float2(alpha * acc[mt][nt][0], alpha * acc[mt][nt][1]);
            float2 v1 = make_float2(alpha * acc[mt][nt][2], alpha * acc[mt][nt][3]);
            size_t o0 = (size_t)r * N + cc;
            size_t o1 = (size_t)(r + 8) * N + cc;
            if (OUTHALF) {
                *(__half2*)(Ch + o0) = __floats2half2_rn(v0.x, v0.y);
                *(__half2*)(Ch + o1) = __floats2half2_rn(v1.x, v1.y);
            } else {
                if (RES) {
                    float2 r0 = *(const float2*)(resp + o0);
                    float2 r1 = *(const float2*)(resp + o1);
                    v0.x += r0.x; v0.y += r0.y;
                    v1.x += r1.x; v1.y += r1.y;
                }
                *(float2*)(Cf + o0) = v0;
                *(float2*)(Cf + o1) = v1;
            }
        }
    }
}

// ---------------- tf32 tensor-core causal flash attention ----------------------
__global__ void __launch_bounds__(256, 2) fattn_kernel(
    const float* __restrict__ Q, const float* __restrict__ K,
    const float* __restrict__ V, float* __restrict__ O) {
    int b = blockIdx.z, h = blockIdx.y;
    int q0 = (gridDim.x - 1 - blockIdx.x) * 128;
    __shared__ float Ks[64 * 68];
    __shared__ float Vs[64 * 72];
    int tid = threadIdx.x, lane = tid & 31, w = tid >> 5;
    int lq = lane >> 2, lr = lane & 3;
    int wrow = q0 + w * 16;

    float qf[8][4];
    const float* Qb = Q + ((size_t)(b * SS + wrow)) * DD + h * DHD;
#pragma unroll
    for (int ks = 0; ks < 8; ks++) {
        qf[ks][0] = tf32r(0.125f * Qb[lq * DD + ks * 8 + lr]);
        qf[ks][1] = tf32r(0.125f * Qb[(lq + 8) * DD + ks * 8 + lr]);
        qf[ks][2] = tf32r(0.125f * Qb[lq * DD + ks * 8 + lr + 4]);
        qf[ks][3] = tf32r(0.125f * Qb[(lq + 8) * DD + ks * 8 + lr + 4]);
    }
    float of[8][4];
#pragma unroll
    for (int dt = 0; dt < 8; dt++) {
        of[dt][0] = 0.f; of[dt][1] = 0.f; of[dt][2] = 0.f; of[dt][3] = 0.f;
    }
    float m0 = -1e30f, m1 = -1e30f, l0 = 0.f, l1 = 0.f;

    int ntiles = q0 / 64 + 2;
    for (int ti = 0; ti < ntiles; ti++) {
        int j0 = ti * 64;
        __syncthreads();
#pragma unroll
        for (int i = 0; i < 4; i++) {
            int f = tid + 256 * i;
            int r = f >> 4, c4 = (f & 15) * 4;
            size_t goff = ((size_t)(b * SS + j0 + r)) * DD + h * DHD + c4;
            sts4_tf32(&Ks[r * 68 + c4], *(const float4*)(K + goff));
            sts4_tf32(&Vs[r * 72 + c4], *(const float4*)(V + goff));
        }
        __syncthreads();
        if (j0 > wrow + 15) continue;

        float sc[8][4];
#pragma unroll
        for (int nt = 0; nt < 8; nt++) {
            sc[nt][0] = 0.f; sc[nt][1] = 0.f; sc[nt][2] = 0.f; sc[nt][3] = 0.f;
        }
#pragma unroll
        for (int nt = 0; nt < 8; nt++)
#pragma unroll
            for (int ks = 0; ks < 8; ks++) {
                float bf[2];
                bf[0] = Ks[(nt * 8 + lq) * 68 + ks * 8 + lr];
                bf[1] = Ks[(nt * 8 + lq) * 68 + ks * 8 + lr + 4];
                mma8(sc[nt], qf[ks], bf);
            }
        if (j0 + 63 > wrow) {
            int r0 = wrow + lq, r1 = r0 + 8;
#pragma unroll
            for (int nt = 0; nt < 8; nt++) {
                int col = j0 + nt * 8 + 2 * lr;
                if (col > r0)     sc[nt][0] = -1e30f;
                if (col + 1 > r0) sc[nt][1] = -1e30f;
                if (col > r1)     sc[nt][2] = -1e30f;
                if (col + 1 > r1) sc[nt][3] = -1e30f;
            }
        }
        float mx0 = -1e30f, mx1 = -1e30f;
#pragma unroll
        for (int nt = 0; nt < 8; nt++) {
            mx0 = fmaxf(mx0, fmaxf(sc[nt][0], sc[nt][1]));
            mx1 = fmaxf(mx1, fmaxf(sc[nt][2], sc[nt][3]));
        }
        mx0 = fmaxf(mx0, __shfl_xor_sync(0xffffffffu, mx0, 1));
        mx0 = fmaxf(mx0, __shfl_xor_sync(0xffffffffu, mx0, 2));
        mx1 = fmaxf(mx1, __shfl_xor_sync(0xffffffffu, mx1, 1));
        mx1 = fmaxf(mx1, __shfl_xor_sync(0xffffffffu, mx1, 2));
        float mn0 = fmaxf(m0, mx0), mn1 = fmaxf(m1, mx1);
        float f0 = __expf(m0 - mn0), f1 = __expf(m1 - mn1);
        m0 = mn0; m1 = mn1;
        l0 *= f0; l1 *= f1;
#pragma unroll
        for (int dt = 0; dt < 8; dt++) {
            of[dt][0] *= f0; of[dt][1] *= f0;
            of[dt][2] *= f1; of[dt][3] *= f1;
        }
        float rs0 = 0.f, rs1 = 0.f;
#pragma unroll
        for (int nt = 0; nt < 8; nt++) {
            float p0 = tf32r(__expf(sc[nt][0] - m0));
            float p1 = tf32r(__expf(sc[nt][1] - m0));
            float p2 = tf32r(__expf(sc[nt][2] - m1));
            float p3 = tf32r(__expf(sc[nt][3] - m1));
            sc[nt][0] = p0; sc[nt][1] = p1; sc[nt][2] = p2; sc[nt][3] = p3;
            rs0 += p0 + p1; rs1 += p2 + p3;
        }
        rs0 += __shfl_xor_sync(0xffffffffu, rs0, 1);
        rs0 += __shfl_xor_sync(0xffffffffu, rs0, 2);
        rs1 += __shfl_xor_sync(0xffffffffu, rs1, 1);
        rs1 += __shfl_xor_sync(0xffffffffu, rs1, 2);
        l0 += rs0; l1 += rs1;
        int srcA = (lane & ~3) | (lr >> 1);
        int srcB = srcA | 2;
        bool odd = (lr & 1) != 0;
#pragma unroll
        for (int nt = 0; nt < 8; nt++) {
            float t00 = __shfl_sync(0xffffffffu, sc[nt][0], srcA);
            float t01 = __shfl_sync(0xffffffffu, sc[nt][1], srcA);
            float t02 = __shfl_sync(0xffffffffu, sc[nt][2], srcA);
            float t03 = __shfl_sync(0xffffffffu, sc[nt][3], srcA);
            float u00 = __shfl_sync(0xffffffffu, sc[nt][0], srcB);
            float u01 = __shfl_sync(0xffffffffu, sc[nt][1], srcB);
            float u02 = __shfl_sync(0xffffffffu, sc[nt][2], srcB);
            float u03 = __shfl_sync(0xffffffffu, sc[nt][3], srcB);
            float pa[4];
            pa[0] = odd ? t01 : t00;
            pa[1] = odd ? t03 : t02;
            pa[2] = odd ? u01 : u00;
            pa[3] = odd ? u03 : u02;
#pragma unroll
            for (int dt = 0; dt < 8; dt++) {
                float bf[2];
                bf[0] = Vs[(nt * 8 + lr) * 72 + dt * 8 + lq];
                bf[1] = Vs[(nt * 8 + lr + 4) * 72 + dt * 8 + lq];
                mma8(of[dt], pa, bf);
            }
        }
    }
    float inv0 = 1.f / l0, inv1 = 1.f / l1;
    float* Ob0 = O + ((size_t)(b * SS + wrow + lq)) * DD + h * DHD;
    float* Ob1 = Ob0 + (size_t)8 * DD;
#pragma unroll
    for (int dt = 0; dt < 8; dt++) {
        *(float2*)&Ob0[dt * 8 + 2 * lr] = make_float2(of[dt][0] * inv0, of[dt][1] * inv0);
        *(float2*)&Ob1[dt * 8 + 2 * lr] = make_float2(of[dt][2] * inv1, of[dt][3] * inv1);
    }
}

// ---------------- top-8 over fp16 scores + gather + residual -------------------
__global__ void __launch_bounds__(256) topk4_kernel(const __half* __restrict__ ms,
                                                    const float* __restrict__ x1,
                                                    const float* __restrict__ KV,
                                                    float* __restrict__ out) {
    int token = blockIdx.x;
    int tid = threadIdx.x, w = tid >> 5, lane = tid & 31;
    const __half* row = ms + (size_t)token * NKK;
    float r[16];
#pragma unroll
    for (int i = 0; i < 4; i++) {
        uint2 u = *(const uint2*)(row + w * 512 + i * 128 + lane * 4);
        float2 f01 = __half22float2(*(const __half2*)&u.x);
        float2 f23 = __half22float2(*(const __half2*)&u.y);
        r[i * 4 + 0] = f01.x; r[i * 4 + 1] = f01.y;
        r[i * 4 + 2] = f23.x; r[i * 4 + 3] = f23.y;
    }
    __shared__ float cv_s[64];
    __shared__ int   ci_s[64];
    __shared__ float tv[TK];
    __shared__ int   tix[TK];
    __shared__ float w8[TK];
    uint32_t taken = 0;
    for (int k = 0; k < TK; k++) {
        float bv = -1e30f; int bi = 0;
#pragma unroll
        for (int i = 0; i < 16; i++) {
            if (!((taken >> i) & 1u) && r[i] > bv) { bv = r[i]; bi = i; }
        }
        int mygi = w * 512 + (bi >> 2) * 128 + lane * 4 + (bi & 3);
        float rv = bv; int gi = mygi;
#pragma unroll
        for (int o = 16; o; o >>= 1) {
            float ov = __shfl_xor_sync(0xffffffffu, rv, o);
            int   oi = __shfl_xor_sync(0xffffffffu, gi, o);
            if (ov > rv || (ov == rv && oi < gi)) { rv = ov; gi = oi; }
        }
        if (gi == mygi) taken |= 1u << bi;
        if (lane == 0) { cv_s[w * 8 + k] = rv; ci_s[w * 8 + k] = gi; }
    }
    __syncthreads();
    if (w == 0) {
        float c0 = cv_s[lane], c1 = cv_s[lane + 32];
        int i0 = ci_s[lane], i1 = ci_s[lane + 32];
        uint32_t tk = 0;
        for (int k = 0; k < TK; k++) {
            float bv = -1e30f; int gi = 0x7fffffff; int sel = -1;
            if (!(tk & 1u)) { bv = c0; gi = i0; sel = 0; }
            if (!(tk & 2u) && (c1 > bv || (c1 == bv && i1 < gi))) {
                bv = c1; gi = i1; sel = 1;
            }
            float rv = bv; int g = gi;
#pragma unroll
            for (int o = 16; o; o >>= 1) {
                float ov = __shfl_xor_sync(0xffffffffu, rv, o);
                int   oi = __shfl_xor_sync(0xffffffffu, g, o);
                if (ov > rv || (ov == rv && oi < g)) { rv = ov; g = oi; }
            }
            if (sel >= 0 && g == gi) tk |= (sel ? 2u : 1u);
            if (lane == 0) { tv[k] = rv; tix[k] = g; }
        }
        if (lane == 0) {
            float mx = tv[0];
            float e[TK], s = 0.f;
            for (int k = 0; k < TK; k++) { e[k] = __expf(tv[k] - mx); s += e[k]; }
            float inv = 1.f / s;
            for (int k = 0; k < TK; k++) w8[k] = e[k] * inv;
        }
    }
    __syncthreads();
    {
        float4 acc = *(const float4*)(x1 + (size_t)token * DD + tid * 4);
#pragma unroll
        for (int k = 0; k < TK; k++) {
            float4 kv = *(const float4*)(KV + (size_t)tix[k] * DD + tid * 4);
            float wk = w8[k];
            acc.x += wk * kv.x; acc.y += wk * kv.y;
            acc.z += wk * kv.z; acc.w += wk * kv.w;
        }
        *(float4*)(out + (size_t)token * DD + tid * 4) = acc;
    }
}

// ---------------- driver --------------------------------------------------------
extern "C" void kernel_launch(void* const* d_in, const int* in_sizes, int n_in,
                              void* d_out, int out_size) {
    const float* x   = (const float*)d_in[0];
    const float* imp = (const float*)d_in[1];
    const float* Wc  = (const float*)d_in[2];
    const float* WQ  = (const float*)d_in[3];
    const float* WK  = (const float*)d_in[4];
    const float* WV  = (const float*)d_in[5];
    const float* Wm  = (const float*)d_in[6];
    const float* CN  = (const float*)d_in[7];
    const float* EP  = (const float*)d_in[8];
    const float* kK  = (const float*)d_in[9];
    const float* kV  = (const float*)d_in[10];
    const float* WO  = (const float*)d_in[11];
    const float* g1  = (const float*)d_in[12];
    const float* b1  = (const float*)d_in[13];
    const float* g2  = (const float*)d_in[14];
    const float* b2  = (const float*)d_in[15];
    float* out = (float*)d_out;

    float *nx, *nx2, *w, *wm, *sc, *mc, *h, *qm, *eq, *ek, *ev;
    float *q, *k, *v, *ao, *x1, *msb, *lgp;
    cudaGetSymbolAddress((void**)&nx,  g_nx);
    cudaGetSymbolAddress((void**)&nx2, g_nx2);
    cudaGetSymbolAddress((void**)&w,   g_w);
    cudaGetSymbolAddress((void**)&wm,  g_wm);
    cudaGetSymbolAddress((void**)&sc,  g_sc);
    cudaGetSymbolAddress((void**)&mc,  g_mc);
    cudaGetSymbolAddress((void**)&h,   g_h);
    cudaGetSymbolAddress((void**)&qm,  g_qm);
    cudaGetSymbolAddress((void**)&eq,  g_eq);
    cudaGetSymbolAddress((void**)&ek,  g_ek);
    cudaGetSymbolAddress((void**)&ev,  g_ev);
    cudaGetSymbolAddress((void**)&q,   g_q);
    cudaGetSymbolAddress((void**)&k,   g_k);
    cudaGetSymbolAddress((void**)&v,   g_v);
    cudaGetSymbolAddress((void**)&ao,  g_ao);
    cudaGetSymbolAddress((void**)&x1,  g_x1);
    cudaGetSymbolAddress((void**)&msb, g_ms);
    cudaGetSymbolAddress((void**)&lgp, g_lgp);

    const long SD = (long)SS * DD;
    const long DR = (long)DD * RR;
    const long SR = (long)SS * RR;
    const long SNK = (long)SS * NKK;

    // ---- attention sub-block ----
    ln_kernel<<<BB * SS, 256>>>(x, g1, b1, nx);
    zeroall_kernel<<<1024, 256>>>((float4*)h, (float4*)qm, (float4*)lgp, w, wm);
    route6_kernel<<<dim3(TT / 16, 4), 256>>>(nx, Wc, WQ, WK, WV, 64, lgp);
    pool4_kernel<<<TT / 4, 256>>>(lgp, imp, 4, w);
    norm_kernel<<<1, 32>>>(w, 4 * BB);
    mixfused2_kernel<<<2048, 256>>>(w, CN, EP, sc, eq, ek, ev);
    // h = nx @ sc : split-K x2, 128 CTAs
    splitk_kernel<<<dim3(RR / 128, SS / 128, 4), 256>>>(
        nx, sc, h, RR, DD / 2, DD, RR, SD, DR, SR);
    qkv_kernel<<<dim3(DD / 128, SS / 128, 6), 256>>>(h, eq, ek, ev, q, k, v);
    fattn_kernel<<<dim3(SS / 128, HH, BB), 256>>>(q, k, v, ao);
    // x1 = x + ao @ WO^T : fp16 NT
    hgemm_nt_kernel<true, false><<<dim3(DD / 128, (BB * SS) / 128, 1), 256>>>(
        ao, WO, x, x1, DD, DD, DD, DD, 1.f, 0, 0, 0, 0);

    // ---- memory sub-block ----
    ln_kernel<<<BB * SS, 256>>>(x1, g2, b2, nx2);
    route6_kernel<<<dim3(TT / 16, 4), 256>>>(nx2, Wm, Wm, Wm, Wm, 16, lgp);
    pool4_kernel<<<TT / 4, 256>>>(lgp, imp, 1, wm);
    norm_kernel<<<1, 32>>>(wm, BB);
    mix2_kernel<<<1024, 256>>>(wm, CN, mc);
    // Qm = nx2 @ mc : split-K x2
    splitk_kernel<<<dim3(RR / 128, SS / 128, 4), 256>>>(
        nx2, mc, qm, RR, DD / 2, DD, RR, SD, DR, SR);
    // ms = Qm @ kK^T / sqrt(256) : fp16 NT, fp16 out
    hgemm_nt_kernel<false, true><<<dim3(NKK / 128, SS / 128, BB), 256>>>(
        qm, kK, nullptr, msb, NKK, RR, RR, RR, 0.0625f, SR, 0, SNK, 0);
    topk4_kernel<<<BB * SS, 256>>>((const __half*)msb, x1, kV, out);
}